// round 12
// baseline (speedup 1.0000x reference)
#include <cuda_runtime.h>
#include <cstdint>

#define EXP2C 0.1803368801111204f   /* (1/8) * log2(e) */

// ================= pools / scratch =================
#define OFF_X   0
#define OFF_C1  2097152
#define OFF_C2  4194304
#define OFF_C3  7340032
#define OFF_AO  9437184
#define OFF_WQ  11534336
#define OFF_WK1 11796480
#define OFF_WV1 12058624
#define OFF_WK2 12320768
#define OFF_WV2 12713984
#define OFF_WK3 13107200
#define OFF_WV3 13238272
#define OFF_WO  13369344
#define POOL_N  13631488

__device__ uint16_t g_h[POOL_N];
__device__ uint16_t g_l[POOL_N];
__device__ uint16_t g_qb[4 * 1024 * 512];
__device__ uint16_t g_kb[4 * 4096 * 512];
__device__ float    g_v[4 * 4096 * 512];
__device__ uint32_t g_mbits[4 * 1024 * 128];
__device__ int      g_mask_is_byte;

// ================= helpers =================
__device__ __forceinline__ uint32_t smem_u32(const void* p) {
    uint32_t a;
    asm("{ .reg .u64 t; cvta.to.shared.u64 t, %1; cvt.u32.u64 %0, t; }" : "=r"(a) : "l"(p));
    return a;
}
#define CP16(dst, src) \
    asm volatile("cp.async.cg.shared.global [%0], [%1], 16;" :: "r"(dst), "l"(src))
#define CP8(dst, src) \
    asm volatile("cp.async.ca.shared.global [%0], [%1], 8;" :: "r"(dst), "l"(src))
#define CP_COMMIT() asm volatile("cp.async.commit_group;" ::: "memory")
#define CP_WAIT(n)  asm volatile("cp.async.wait_group %0;" :: "n"(n) : "memory")

__device__ __forceinline__ float tf32_rn(float x) {
    return __uint_as_float((__float_as_uint(x) + 0x1000u) & 0xFFFFE000u);
}
__device__ __forceinline__ float tf32_cvt(float x) {
    uint32_t r;
    asm("cvt.rna.tf32.f32 %0, %1;" : "=r"(r) : "f"(x));
    return __uint_as_float(r);
}
__device__ __forceinline__ float bf16_rn(float x) {
    uint32_t u = __float_as_uint(x);
    u += 0x7FFFu + ((u >> 16) & 1u);
    return __uint_as_float(u & 0xFFFF0000u);
}
__device__ __forceinline__ uint32_t pkh(float a, float b) {
    return (__float_as_uint(b) & 0xFFFF0000u) | (__float_as_uint(a) >> 16);
}
__device__ __forceinline__ uint32_t bf2(float a, float b) {
    uint32_t r;
    asm("cvt.rn.bf16x2.f32 %0, %1, %2;" : "=r"(r) : "f"(b), "f"(a));
    return r;
}
__device__ __forceinline__ float ex2f(float y) {
    float r;
    asm("ex2.approx.f32 %0, %1;" : "=f"(r) : "f"(y));
    return r;
}
__device__ __forceinline__ void mma8(float* c, const uint32_t* a, const uint32_t* b) {
    asm volatile("mma.sync.aligned.m16n8k8.row.col.f32.tf32.tf32.f32 "
        "{%0,%1,%2,%3},{%4,%5,%6,%7},{%8,%9},{%0,%1,%2,%3};"
        : "+f"(c[0]), "+f"(c[1]), "+f"(c[2]), "+f"(c[3])
        : "r"(a[0]), "r"(a[1]), "r"(a[2]), "r"(a[3]), "r"(b[0]), "r"(b[1]));
}
__device__ __forceinline__ void mma16(float* c, const uint32_t* a, const uint32_t* b) {
    asm volatile("mma.sync.aligned.m16n8k16.row.col.f32.bf16.bf16.f32 "
        "{%0,%1,%2,%3},{%4,%5,%6,%7},{%8,%9},{%0,%1,%2,%3};"
        : "+f"(c[0]), "+f"(c[1]), "+f"(c[2]), "+f"(c[3])
        : "r"(a[0]), "r"(a[1]), "r"(a[2]), "r"(a[3]), "r"(b[0]), "r"(b[1]));
}
__device__ __forceinline__ void ldsm_x4(uint32_t* r, uint32_t addr) {
    asm volatile("ldmatrix.sync.aligned.m8n8.x4.shared.b16 {%0,%1,%2,%3}, [%4];"
        : "=r"(r[0]), "=r"(r[1]), "=r"(r[2]), "=r"(r[3]) : "r"(addr));
}
__device__ __forceinline__ void ldsm_x4_t(uint32_t* r, uint32_t addr) {
    asm volatile("ldmatrix.sync.aligned.m8n8.x4.trans.shared.b16 {%0,%1,%2,%3}, [%4];"
        : "=r"(r[0]), "=r"(r[1]), "=r"(r[2]), "=r"(r[3]) : "r"(addr));
}

// ================= mask detect + bit-pack =================
__global__ void detect_mask_kernel(const unsigned char* __restrict__ m) {
    __shared__ int any;
    if (threadIdx.x == 0) any = 0;
    __syncthreads();
    int found = 0;
    for (int i = threadIdx.x; i < 4096; i += blockDim.x)
        if ((i & 3) == 1 && m[i]) found = 1;
    if (found) atomicOr(&any, 1);
    __syncthreads();
    if (threadIdx.x == 0) g_mask_is_byte = any;
}

__global__ void pack_mask_kernel(const void* __restrict__ m1, const void* __restrict__ m2,
                                 const void* __restrict__ m3) {
    int idx = blockIdx.x * blockDim.x + threadIdx.x;
    if (idx >= 4 * 1024 * 128) return;
    int w = idx & 127, q = (idx >> 7) & 1023, b = idx >> 17;
    int k0 = w * 32;
    const void* mp; int nseg, jl;
    if (k0 < 1024)      { mp = m1; nseg = 1024; jl = k0; }
    else if (k0 < 2048) { mp = m2; nseg = 1024; jl = k0 - 1024; }
    else                { mp = m3; nseg = 2048; jl = k0 - 2048; }
    size_t base = (size_t)(b * 1024 + q) * nseg + jl;
    uint32_t bits = 0;
    if (g_mask_is_byte) {
        const uint4* p = (const uint4*)((const unsigned char*)mp + base);
        uint4 a = p[0], c = p[1];
        uint32_t ws[8] = {a.x, a.y, a.z, a.w, c.x, c.y, c.z, c.w};
#pragma unroll
        for (int wi = 0; wi < 8; ++wi)
#pragma unroll
            for (int by = 0; by < 4; ++by)
                if ((ws[wi] >> (8 * by)) & 0xFFu) bits |= 1u << (wi * 4 + by);
    } else {
        const uint4* p = (const uint4*)((const uint32_t*)mp + base);
#pragma unroll
        for (int wi = 0; wi < 8; ++wi) {
            uint4 v = p[wi];
            if (v.x) bits |= 1u << (wi * 4 + 0);
            if (v.y) bits |= 1u << (wi * 4 + 1);
            if (v.z) bits |= 1u << (wi * 4 + 2);
            if (v.w) bits |= 1u << (wi * 4 + 3);
        }
    }
    g_mbits[idx] = bits;
}

// ================= bf16 hi/lo split (pre-pass) =================
struct SplitJobs {
    const float* src[12];
    int nblk[13];
    int off[12];
};
__global__ __launch_bounds__(256) void split_kernel(SplitJobs j, int njobs) {
    int bid = blockIdx.x;
    int ji = 0;
    while (ji + 1 < njobs && bid >= j.nblk[ji + 1]) ++ji;
    int local = bid - j.nblk[ji];
    const float4* src = (const float4*)j.src[ji];
    uint2* dh = (uint2*)(g_h + j.off[ji]);
    uint2* dl = (uint2*)(g_l + j.off[ji]);
    size_t base4 = (size_t)local * 1024;
#pragma unroll
    for (int it = 0; it < 4; ++it) {
        size_t i4 = base4 + it * 256 + threadIdx.x;
        float4 v = src[i4];
        float h0 = bf16_rn(v.x), h1 = bf16_rn(v.y), h2 = bf16_rn(v.z), h3 = bf16_rn(v.w);
        dh[i4] = make_uint2(pkh(h0, h1), pkh(h2, h3));
        dl[i4] = make_uint2(bf2(v.x - h0, v.y - h1), bf2(v.z - h2, v.w - h3));
    }
}

// ================= 3xBF16 HMMA GEMM, job-table, cp.async 2-stage =================
#define G_OAL 4608
#define G_OBH 9216
#define G_OBL 11520
#define G_STW 13824
struct GJobs {
    const uint16_t* Ah[7]; const uint16_t* Al[7];
    const uint16_t* Wh[7]; const uint16_t* Wl[7];
    const float* bias[7];  void* C[7];
    int K[7], Mb[7], rowOff[7], bStride[7], mode[7];
    int blk0[8];
    int njobs;
};
// mode: 0 = fp32 out, 1 = tf32-rounded fp32 out, 2 = bf16 out, 4 = bf16 out scaled by EXP2C
__global__ __launch_bounds__(256, 2) void gemm_jobs(GJobs J) {
    extern __shared__ uint32_t smw[];
    int j = 0;
    while (j + 1 < J.njobs && (int)blockIdx.x >= J.blk0[j + 1]) ++j;
    const int lb = blockIdx.x - J.blk0[j];
    const uint16_t* __restrict__ Ah = J.Ah[j];
    const uint16_t* __restrict__ Al = J.Al[j];
    const uint16_t* __restrict__ Wh = J.Wh[j];
    const uint16_t* __restrict__ Wl = J.Wl[j];
    const float* __restrict__ bias = J.bias[j];
    void* Cv = J.C[j];
    const int K = J.K[j], Mb = J.Mb[j], rowOff = J.rowOff[j];
    const int bStride = J.bStride[j], mode = J.mode[j];

    const int tid = threadIdx.x, lane = tid & 31, wid = tid >> 5;
    const int wm = wid & 3, wn = wid >> 2;
    const int lr = lane >> 2, lc = lane & 3;
    const int m0 = (lb >> 3) * 128, n0 = (lb & 7) * 64;
    const int l16 = lane & 15, lh8 = (lane >> 4) << 3;

    float acc[2][4][4];
#pragma unroll
    for (int i = 0; i < 2; ++i)
#pragma unroll
        for (int jj = 0; jj < 4; ++jj)
#pragma unroll
            for (int e = 0; e < 4; ++e) acc[i][jj][e] = 0.f;

    const int nK = K >> 6;
    const uint32_t ub = smem_u32(smw);

#define STAGE(c, s) do { \
    const uint32_t d0 = ub + (s) * G_STW * 4; \
    _Pragma("unroll") \
    for (int it = 0; it < 4; ++it) { \
        int id = it * 256 + tid, row = id >> 3, seg = id & 7; \
        size_t so = (size_t)(m0 + row) * K + (c) * 64 + seg * 8; \
        uint32_t dw = (row * 36 + seg * 4) * 4; \
        CP16(d0 + dw, Ah + so); \
        CP16(d0 + G_OAL * 4 + dw, Al + so); \
    } \
    _Pragma("unroll") \
    for (int it = 0; it < 2; ++it) { \
        int id = it * 256 + tid, row = id >> 3, seg = id & 7; \
        size_t so = (size_t)((c) * 64 + row) * 512 + n0 + seg * 8; \
        uint32_t dw = (row * 36 + seg * 4) * 4; \
        CP16(d0 + G_OBH * 4 + dw, Wh + so); \
        CP16(d0 + G_OBL * 4 + dw, Wl + so); \
    } \
    CP_COMMIT(); \
} while (0)

    STAGE(0, 0);
    for (int c = 0; c < nK; ++c) {
        const int s = c & 1;
        if (c + 1 < nK) { STAGE(c + 1, s ^ 1); CP_WAIT(1); }
        else            { CP_WAIT(0); }
        __syncthreads();
        const uint32_t sb = ub + s * G_STW * 4;
#pragma unroll
        for (int st = 0; st < 4; ++st) {
            const int k0 = st * 16;
            uint32_t ah[2][4], al_[2][4], bh[2][4], bl_[2][4];
#pragma unroll
            for (int mf = 0; mf < 2; ++mf) {
                int row = wm * 32 + mf * 16 + l16;
                uint32_t ad = sb + (row * 36 + ((k0 + lh8) >> 1)) * 4;
                ldsm_x4(ah[mf], ad);
                ldsm_x4(al_[mf], ad + G_OAL * 4);
            }
#pragma unroll
            for (int p = 0; p < 2; ++p) {
                int row = k0 + l16;
                int col = wn * 32 + p * 16 + lh8;
                uint32_t bd = sb + (G_OBH + row * 36 + (col >> 1)) * 4;
                ldsm_x4_t(bh[p], bd);
                ldsm_x4_t(bl_[p], bd + (G_OBL - G_OBH) * 4);
            }
#pragma unroll
            for (int mf = 0; mf < 2; ++mf)
#pragma unroll
                for (int p = 0; p < 2; ++p) {
                    mma16(acc[mf][p * 2 + 0], ah[mf], &bh[p][0]);
                    mma16(acc[mf][p * 2 + 1], ah[mf], &bh[p][2]);
                    mma16(acc[mf][p * 2 + 0], ah[mf], &bl_[p][0]);
                    mma16(acc[mf][p * 2 + 1], ah[mf], &bl_[p][2]);
                    mma16(acc[mf][p * 2 + 0], al_[mf], &bh[p][0]);
                    mma16(acc[mf][p * 2 + 1], al_[mf], &bh[p][2]);
                }
        }
        __syncthreads();
    }
#undef STAGE
#pragma unroll
    for (int mf = 0; mf < 2; ++mf) {
        int r = m0 + wm * 32 + mf * 16 + lr;
        int b0i = r / Mb;
        size_t or0 = (size_t)b0i * bStride + rowOff + (r - b0i * Mb);
        int r2 = r + 8;
        int b1i = r2 / Mb;
        size_t or1 = (size_t)b1i * bStride + rowOff + (r2 - b1i * Mb);
#pragma unroll
        for (int nf = 0; nf < 4; ++nf) {
            int col = n0 + wn * 32 + nf * 8 + 2 * lc;
            float bv0 = bias[col], bv1 = bias[col + 1];
            float v00 = acc[mf][nf][0] + bv0, v01 = acc[mf][nf][1] + bv1;
            float v10 = acc[mf][nf][2] + bv0, v11 = acc[mf][nf][3] + bv1;
            if (mode >= 2) {
                if (mode == 4) { v00 *= EXP2C; v01 *= EXP2C; v10 *= EXP2C; v11 *= EXP2C; }
                uint16_t* Cb = (uint16_t*)Cv;
                *(uint32_t*)(Cb + or0 * 512 + col) = pkh(bf16_rn(v00), bf16_rn(v01));
                *(uint32_t*)(Cb + or1 * 512 + col) = pkh(bf16_rn(v10), bf16_rn(v11));
            } else {
                float* C = (float*)Cv;
                if (mode == 1) {
                    v00 = tf32_rn(v00); v01 = tf32_rn(v01);
                    v10 = tf32_rn(v10); v11 = tf32_rn(v11);
                }
                *(float2*)(C + or0 * 512 + col) = make_float2(v00, v01);
                *(float2*)(C + or1 * 512 + col) = make_float2(v10, v11);
            }
        }
    }
}

// ================= flash attention: 128q x 64k, fragment-major P =================
// 256 thr = 8 warps (4m x 2n). P stored in PV a-fragment order -> LDS.128 reads.
#define A_QW 0
#define A_KW 4608
#define A_VW 9216
#define A_PW 18432
#define A_MW 27136
#define A_LW 27648
#define A_TOTW 27904
#define AV 72

__global__ __launch_bounds__(256, 2) void attn_mma(
    const uint16_t* __restrict__ qb, const uint16_t* __restrict__ kb,
    const float* __restrict__ vb,
    uint16_t* __restrict__ oh, uint16_t* __restrict__ ol)
{
    extern __shared__ uint32_t smw[];
    float* smf = (float*)smw;
    uint32_t* sM = smw + A_MW;
    float* sP = smf + A_PW;      // fragment-major: [g(8)][ks(8)][lr(8)][lc(4)][elem(4)]
    float* sL = smf + A_LW;
    const float4* PF = (const float4*)sP;

    const int tid = threadIdx.x, lane = tid & 31, wid = tid >> 5;
    const int wm = wid & 3, wn = wid >> 2;
    const int lr = lane >> 2, lc = lane & 3;
    const int ln8 = lane & 7;
    const int q0 = blockIdx.x * 128, h = blockIdx.y, b = blockIdx.z;

    const uint16_t* Qg = qb + ((size_t)(b * 1024 + q0)) * 512 + h * 64;
    const uint16_t* Kg = kb + ((size_t)(b * 4096)) * 512 + h * 64;
    const float*    Vg = vb + ((size_t)(b * 4096)) * 512 + h * 64;
    const uint32_t* mbase = g_mbits + ((size_t)(b * 1024 + q0)) * 128;
    const uint32_t ubase = smem_u32(smw);
    const uint32_t uQ = ubase + A_QW * 4, uK = ubase + A_KW * 4;
    const uint32_t uV = ubase + A_VW * 4, uM = ubase + A_MW * 4;

    // ---- prologue: Q(128 rows), K(0), V(0), M(0) ----
#pragma unroll
    for (int it = 0; it < 4; ++it) {
        int id = it * 256 + tid, row = id >> 3, seg = id & 7;
        CP16(uQ + (row * 36 + seg * 4) * 4, Qg + (size_t)row * 512 + seg * 8);
    }
#pragma unroll
    for (int it = 0; it < 2; ++it) {
        int id = it * 256 + tid, row = id >> 3, seg = id & 7;
        CP16(uK + (row * 36 + seg * 4) * 4, Kg + (size_t)row * 512 + seg * 8);
    }
#pragma unroll
    for (int it = 0; it < 4; ++it) {
        int id = it * 256 + tid, row = id >> 4, seg = id & 15;
        CP16(uV + (row * AV + seg * 4) * 4, Vg + (size_t)row * 512 + seg * 4);
    }
    if (tid < 128) CP8(uM + tid * 8, (const char*)(mbase + (size_t)tid * 128));
    CP_COMMIT();
    CP_WAIT(0);
    __syncthreads();

    float o[2][4][4];
    float l_acc[2][2];
#pragma unroll
    for (int i = 0; i < 2; ++i) {
        l_acc[i][0] = 0.f; l_acc[i][1] = 0.f;
#pragma unroll
        for (int jj = 0; jj < 4; ++jj)
#pragma unroll
            for (int e = 0; e < 4; ++e) o[i][jj][e] = 0.f;
    }

    for (int t = 0; t < 64; ++t) {
        const int s = t & 1;
        if (t > 0) { CP_WAIT(0); __syncthreads(); }

        // ---- EARLY stage of tile t+1 into buffer s^1 ----
        if (t < 63) {
            const uint16_t* Kn = Kg + (size_t)(t + 1) * 64 * 512;
            const float* Vn = Vg + (size_t)(t + 1) * 64 * 512;
            const uint32_t dK = uK + (s ^ 1) * 2304 * 4;
            const uint32_t dV = uV + (s ^ 1) * 64 * AV * 4;
#pragma unroll
            for (int it = 0; it < 2; ++it) {
                int id = it * 256 + tid, row = id >> 3, seg = id & 7;
                CP16(dK + (row * 36 + seg * 4) * 4, Kn + (size_t)row * 512 + seg * 8);
            }
#pragma unroll
            for (int it = 0; it < 4; ++it) {
                int id = it * 256 + tid, row = id >> 4, seg = id & 15;
                CP16(dV + (row * AV + seg * 4) * 4, Vn + (size_t)row * 512 + seg * 4);
            }
            if (tid < 128)
                CP8(uM + (s ^ 1) * 1024 + tid * 8,
                    (const char*)(mbase + (size_t)tid * 128 + (t + 1) * 2));
            CP_COMMIT();
        }

        // ---- S' = (Q*EXP2C) K^T (bf16 m16n8k16); exponent-ready ----
        const uint32_t uKs = uK + s * 2304 * 4;
        float sv[2][4][4];
#pragma unroll
        for (int i = 0; i < 2; ++i)
#pragma unroll
            for (int jj = 0; jj < 4; ++jj)
#pragma unroll
                for (int e = 0; e < 4; ++e) sv[i][jj][e] = 0.f;
#pragma unroll
        for (int ks = 0; ks < 4; ++ks) {
            int kcb = ks * 16 + ((lane >> 3) & 1) * 8;
            int nrow = wn * 32 + (lane >> 4) * 8 + ln8;
            uint32_t bk0[4], bk1[4];
            ldsm_x4(bk0, uKs + (nrow * 36 + (kcb >> 1)) * 4);
            ldsm_x4(bk1, uKs + ((nrow + 16) * 36 + (kcb >> 1)) * 4);
#pragma unroll
            for (int mf = 0; mf < 2; ++mf) {
                int qrow = wm * 32 + mf * 16 + ((lane >> 3) & 1) * 8 + ln8;
                int kc = ks * 16 + (lane >> 4) * 8;
                uint32_t aq[4];
                ldsm_x4(aq, uQ + (qrow * 36 + (kc >> 1)) * 4);
                mma16(sv[mf][0], aq, &bk0[0]);
                mma16(sv[mf][1], aq, &bk0[2]);
                mma16(sv[mf][2], aq, &bk1[0]);
                mma16(sv[mf][3], aq, &bk1[2]);
            }
        }

        // ---- masked no-max softmax + fragment-major P write ----
#pragma unroll
        for (int mf = 0; mf < 2; ++mf)
#pragma unroll
            for (int u = 0; u < 2; ++u) {
                int row = wm * 32 + mf * 16 + lr + u * 8;
                uint32_t mw = sM[s * 256 + row * 2 + wn];
                float rs = 0.f;
#pragma unroll
                for (int nf = 0; nf < 4; ++nf) {
#pragma unroll
                    for (int q2 = 0; q2 < 2; ++q2) {
                        int cr = u * 2 + q2;
                        int cl = nf * 8 + 2 * lc + q2;
                        float p = tf32_cvt(ex2f(sv[mf][nf][cr]));
                        p = ((mw >> cl) & 1u) ? p : 0.f;
                        rs += p;
                        sv[mf][nf][cr] = p;
                    }
                }
                l_acc[mf][u] += rs;
                // frag-major store: g=wm*2+mf, ks=wn*4+nf, elem = u + 2*(lc>>1)
                int gbase = (((wm * 2 + mf) * 8 + wn * 4) * 8 + lr) * 16 + u + 2 * (lc >> 1);
                int c0 = (lc & 1) * 8;   // lc_r*4 for q2=0
#pragma unroll
                for (int nf = 0; nf < 4; ++nf) {
                    sP[gbase + nf * 128 + c0]     = sv[mf][nf][u * 2];
                    sP[gbase + nf * 128 + c0 + 4] = sv[mf][nf][u * 2 + 1];
                }
            }
        __syncthreads();   // P visible

        // ---- O += P @ V (tf32 m16n8k8), P a-frags via LDS.128 ----
        const uint32_t* sVu = smw + A_VW + s * 64 * AV;
#pragma unroll
        for (int ks = 0; ks < 8; ++ks) {
            const int kb0 = ks * 8;
            uint32_t bv[4][2];
#pragma unroll
            for (int nf = 0; nf < 4; ++nf) {
                int drow = wn * 32 + nf * 8 + lr;
                bv[nf][0] = sVu[(kb0 + lc) * AV + drow];
                bv[nf][1] = sVu[(kb0 + 4 + lc) * AV + drow];
            }
#pragma unroll
            for (int mf = 0; mf < 2; ++mf) {
                float4 av = PF[(((wm * 2 + mf) * 8 + ks) * 8 + lr) * 4 + lc];
                uint32_t ap[4] = {__float_as_uint(av.x), __float_as_uint(av.y),
                                  __float_as_uint(av.z), __float_as_uint(av.w)};
#pragma unroll
                for (int nf = 0; nf < 4; ++nf) mma8(o[mf][nf], ap, bv[nf]);
            }
        }
    }

    // ---- l reduce: quads, then the 2 n-warps via smem ----
#pragma unroll
    for (int mf = 0; mf < 2; ++mf)
#pragma unroll
        for (int u = 0; u < 2; ++u) {
            float v = l_acc[mf][u];
            v += __shfl_xor_sync(0xffffffffu, v, 1);
            v += __shfl_xor_sync(0xffffffffu, v, 2);
            l_acc[mf][u] = v;
        }
    if (lc == 0) {
#pragma unroll
        for (int mf = 0; mf < 2; ++mf)
#pragma unroll
            for (int u = 0; u < 2; ++u)
                sL[wn * 128 + wm * 32 + mf * 16 + lr + u * 8] = l_acc[mf][u];
    }
    __syncthreads();

    // normalize + write bf16 h/l planes
    uint16_t* Oh = oh + ((size_t)(b * 1024 + q0)) * 512 + h * 64;
    uint16_t* Ol = ol + ((size_t)(b * 1024 + q0)) * 512 + h * 64;
#pragma unroll
    for (int mf = 0; mf < 2; ++mf)
#pragma unroll
        for (int u = 0; u < 2; ++u) {
            int row = wm * 32 + mf * 16 + lr + u * 8;
            float linv = 1.f / (sL[row] + sL[128 + row]);
#pragma unroll
            for (int nf = 0; nf < 4; ++nf) {
                int col = wn * 32 + nf * 8 + 2 * lc;
                float v0 = o[mf][nf][u * 2] * linv;
                float v1 = o[mf][nf][u * 2 + 1] * linv;
                float h0 = bf16_rn(v0), h1 = bf16_rn(v1);
                *(uint32_t*)(Oh + (size_t)row * 512 + col) = pkh(h0, h1);
                *(uint32_t*)(Ol + (size_t)row * 512 + col) = bf2(v0 - h0, v1 - h1);
            }
        }
}

// ================= launcher =================
extern "C" void kernel_launch(void* const* d_in, const int* in_sizes, int n_in,
                              void* d_out, int out_size) {
    const float* x        = (const float*)d_in[0];
    const float* context  = (const float*)d_in[1];
    const float* context2 = (const float*)d_in[2];
    const float* context3 = (const float*)d_in[3];
    const void*  mask1 = d_in[4];
    const void*  mask2 = d_in[5];
    const void*  mask3 = d_in[6];
    const float* bq  = (const float*)d_in[8];
    const float* bk1 = (const float*)d_in[10];
    const float* bv1 = (const float*)d_in[12];
    const float* bk2 = (const float*)d_in[14];
    const float* bv2 = (const float*)d_in[16];
    const float* bk3 = (const float*)d_in[18];
    const float* bv3 = (const float*)d_in[20];
    const float* Wo  = (const float*)d_in[21];
    const float* bo  = (const float*)d_in[22];
    float* out = (float*)d_out;

    uint16_t *hp, *lp, *qbp, *kbp;
    float *vp;
    cudaGetSymbolAddress((void**)&hp,  g_h);
    cudaGetSymbolAddress((void**)&lp,  g_l);
    cudaGetSymbolAddress((void**)&qbp, g_qb);
    cudaGetSymbolAddress((void**)&kbp, g_kb);
    cudaGetSymbolAddress((void**)&vp,  g_v);

    const int smem_gemm = 2 * G_STW * 4;    // 110592
    const int smem_attn = A_TOTW * 4;       // 111616
    static bool once = false;
    static cudaStream_t s2;
    static cudaEvent_t ev1, ev2;
    if (!once) {
        cudaFuncSetAttribute(gemm_jobs, cudaFuncAttributeMaxDynamicSharedMemorySize, smem_gemm);
        cudaFuncSetAttribute(attn_mma, cudaFuncAttributeMaxDynamicSharedMemorySize, smem_attn);
        cudaStreamCreateWithFlags(&s2, cudaStreamNonBlocking);
        cudaEventCreateWithFlags(&ev1, cudaEventDisableTiming);
        cudaEventCreateWithFlags(&ev2, cudaEventDisableTiming);
        once = true;
    }

    // fork: mask detect + pack on side stream, overlapped with split + GEMMs
    cudaEventRecord(ev1, 0);
    cudaStreamWaitEvent(s2, ev1, 0);
    detect_mask_kernel<<<1, 256, 0, s2>>>((const unsigned char*)mask1);
    pack_mask_kernel<<<2048, 256, 0, s2>>>(mask1, mask2, mask3);
    cudaEventRecord(ev2, s2);

    // pre-split inputs + weights into bf16 h/l planes (main stream)
    {
        SplitJobs js;
        const float* srcs[12] = {x, context, context2, context3,
                                 (const float*)d_in[7], (const float*)d_in[9],
                                 (const float*)d_in[11], (const float*)d_in[13],
                                 (const float*)d_in[15], (const float*)d_in[17],
                                 (const float*)d_in[19], Wo};
        int offs[12] = {OFF_X, OFF_C1, OFF_C2, OFF_C3,
                        OFF_WQ, OFF_WK1, OFF_WV1, OFF_WK2, OFF_WV2,
                        OFF_WK3, OFF_WV3, OFF_WO};
        int cnts[12] = {512, 512, 768, 512, 64, 64, 64, 96, 96, 32, 32, 64};
        int cum = 0;
        for (int i = 0; i < 12; ++i) {
            js.src[i] = srcs[i]; js.off[i] = offs[i];
            js.nblk[i] = cum; cum += cnts[i];
        }
        js.nblk[12] = cum;
        split_kernel<<<cum, 256>>>(js, 12);
    }

    // merged projection GEMMs (7 jobs); Q scaled by EXP2C (mode 4)
    {
        GJobs J;
        int aoffs[7]  = {OFF_X, OFF_C1, OFF_C2, OFF_C3, OFF_C1, OFF_C2, OFF_C3};
        int woffs[7]  = {OFF_WQ, OFF_WK1, OFF_WK2, OFF_WK3, OFF_WV1, OFF_WV2, OFF_WV3};
        const float* biases[7] = {bq, bk1, bk2, bk3, bv1, bv2, bv3};
        void* Cs[7]   = {qbp, kbp, kbp, kbp, vp, vp, vp};
        int Ks[7]     = {512, 512, 768, 256, 512, 768, 256};
        int Mbs[7]    = {1024, 1024, 1024, 2048, 1024, 1024, 2048};
        int ros[7]    = {0, 0, 1024, 2048, 0, 1024, 2048};
        int bss[7]    = {1024, 4096, 4096, 4096, 4096, 4096, 4096};
        int modes[7]  = {4, 2, 2, 2, 1, 1, 1};
        int blks[7]   = {256, 256, 256, 512, 256, 256, 512};
        int cum = 0;
        for (int i = 0; i < 7; ++i) {
            J.Ah[i] = hp + aoffs[i]; J.Al[i] = lp + aoffs[i];
            J.Wh[i] = hp + woffs[i]; J.Wl[i] = lp + woffs[i];
            J.bias[i] = biases[i]; J.C[i] = Cs[i];
            J.K[i] = Ks[i]; J.Mb[i] = Mbs[i]; J.rowOff[i] = ros[i];
            J.bStride[i] = bss[i]; J.mode[i] = modes[i];
            J.blk0[i] = cum; cum += blks[i];
        }
        J.blk0[7] = cum; J.njobs = 7;
        gemm_jobs<<<cum, 256, smem_gemm>>>(J);
    }

    // join mask stream before attention
    cudaStreamWaitEvent(0, ev2, 0);

    // attention -> bf16 h/l planes at OFF_AO
    attn_mma<<<dim3(8, 8, 4), 256, smem_attn>>>(qbp, kbp, vp, hp + OFF_AO, lp + OFF_AO);

    // final projection -> d_out
    {
        GJobs J;
        J.Ah[0] = hp + OFF_AO; J.Al[0] = lp + OFF_AO;
        J.Wh[0] = hp + OFF_WO; J.Wl[0] = lp + OFF_WO;
        J.bias[0] = bo; J.C[0] = out;
        J.K[0] = 512; J.Mb[0] = 1024; J.rowOff[0] = 0;
        J.bStride[0] = 1024; J.mode[0] = 0;
        J.blk0[0] = 0; J.blk0[1] = 256; J.njobs = 1;
        gemm_jobs<<<256, 256, smem_gemm>>>(J);
    }
}

// round 13
// speedup vs baseline: 1.0002x; 1.0002x over previous
#include <cuda_runtime.h>
#include <cstdint>

#define EXP2C 0.1803368801111204f   /* (1/8) * log2(e) */

// ================= pools / scratch =================
#define OFF_X   0
#define OFF_C1  2097152
#define OFF_C2  4194304
#define OFF_C3  7340032
#define OFF_AO  9437184
#define OFF_WQ  11534336
#define OFF_WK1 11796480
#define OFF_WV1 12058624
#define OFF_WK2 12320768
#define OFF_WV2 12713984
#define OFF_WK3 13107200
#define OFF_WV3 13238272
#define OFF_WO  13369344
#define POOL_N  13631488

__device__ uint16_t g_h[POOL_N];
__device__ uint16_t g_l[POOL_N];
__device__ uint16_t g_qb[4 * 1024 * 512];
__device__ uint16_t g_kb[4 * 4096 * 512];
__device__ float    g_v[4 * 4096 * 512];
__device__ uint32_t g_mbits[4 * 1024 * 128];
__device__ int      g_mask_is_byte;

// ================= helpers =================
__device__ __forceinline__ uint32_t smem_u32(const void* p) {
    uint32_t a;
    asm("{ .reg .u64 t; cvta.to.shared.u64 t, %1; cvt.u32.u64 %0, t; }" : "=r"(a) : "l"(p));
    return a;
}
#define CP16(dst, src) \
    asm volatile("cp.async.cg.shared.global [%0], [%1], 16;" :: "r"(dst), "l"(src))
#define CP8(dst, src) \
    asm volatile("cp.async.ca.shared.global [%0], [%1], 8;" :: "r"(dst), "l"(src))
#define CP_COMMIT() asm volatile("cp.async.commit_group;" ::: "memory")
#define CP_WAIT(n)  asm volatile("cp.async.wait_group %0;" :: "n"(n) : "memory")

__device__ __forceinline__ float tf32_rn(float x) {
    return __uint_as_float((__float_as_uint(x) + 0x1000u) & 0xFFFFE000u);
}
__device__ __forceinline__ float tf32_cvt(float x) {
    uint32_t r;
    asm("cvt.rna.tf32.f32 %0, %1;" : "=r"(r) : "f"(x));
    return __uint_as_float(r);
}
__device__ __forceinline__ float bf16_rn(float x) {
    uint32_t u = __float_as_uint(x);
    u += 0x7FFFu + ((u >> 16) & 1u);
    return __uint_as_float(u & 0xFFFF0000u);
}
__device__ __forceinline__ uint32_t pkh(float a, float b) {
    return (__float_as_uint(b) & 0xFFFF0000u) | (__float_as_uint(a) >> 16);
}
__device__ __forceinline__ uint32_t bf2(float a, float b) {
    uint32_t r;
    asm("cvt.rn.bf16x2.f32 %0, %1, %2;" : "=r"(r) : "f"(b), "f"(a));
    return r;
}
__device__ __forceinline__ float ex2f(float y) {
    float r;
    asm("ex2.approx.f32 %0, %1;" : "=f"(r) : "f"(y));
    return r;
}
__device__ __forceinline__ void mma8(float* c, const uint32_t* a, const uint32_t* b) {
    asm volatile("mma.sync.aligned.m16n8k8.row.col.f32.tf32.tf32.f32 "
        "{%0,%1,%2,%3},{%4,%5,%6,%7},{%8,%9},{%0,%1,%2,%3};"
        : "+f"(c[0]), "+f"(c[1]), "+f"(c[2]), "+f"(c[3])
        : "r"(a[0]), "r"(a[1]), "r"(a[2]), "r"(a[3]), "r"(b[0]), "r"(b[1]));
}
__device__ __forceinline__ void mma16(float* c, const uint32_t* a, const uint32_t* b) {
    asm volatile("mma.sync.aligned.m16n8k16.row.col.f32.bf16.bf16.f32 "
        "{%0,%1,%2,%3},{%4,%5,%6,%7},{%8,%9},{%0,%1,%2,%3};"
        : "+f"(c[0]), "+f"(c[1]), "+f"(c[2]), "+f"(c[3])
        : "r"(a[0]), "r"(a[1]), "r"(a[2]), "r"(a[3]), "r"(b[0]), "r"(b[1]));
}
__device__ __forceinline__ void ldsm_x4(uint32_t* r, uint32_t addr) {
    asm volatile("ldmatrix.sync.aligned.m8n8.x4.shared.b16 {%0,%1,%2,%3}, [%4];"
        : "=r"(r[0]), "=r"(r[1]), "=r"(r[2]), "=r"(r[3]) : "r"(addr));
}
__device__ __forceinline__ void ldsm_x4_t(uint32_t* r, uint32_t addr) {
    asm volatile("ldmatrix.sync.aligned.m8n8.x4.trans.shared.b16 {%0,%1,%2,%3}, [%4];"
        : "=r"(r[0]), "=r"(r[1]), "=r"(r[2]), "=r"(r[3]) : "r"(addr));
}

// ================= mask detect + bit-pack =================
__global__ void detect_mask_kernel(const unsigned char* __restrict__ m) {
    __shared__ int any;
    if (threadIdx.x == 0) any = 0;
    __syncthreads();
    int found = 0;
    for (int i = threadIdx.x; i < 4096; i += blockDim.x)
        if ((i & 3) == 1 && m[i]) found = 1;
    if (found) atomicOr(&any, 1);
    __syncthreads();
    if (threadIdx.x == 0) g_mask_is_byte = any;
}

__global__ void pack_mask_kernel(const void* __restrict__ m1, const void* __restrict__ m2,
                                 const void* __restrict__ m3) {
    int idx = blockIdx.x * blockDim.x + threadIdx.x;
    if (idx >= 4 * 1024 * 128) return;
    int w = idx & 127, q = (idx >> 7) & 1023, b = idx >> 17;
    int k0 = w * 32;
    const void* mp; int nseg, jl;
    if (k0 < 1024)      { mp = m1; nseg = 1024; jl = k0; }
    else if (k0 < 2048) { mp = m2; nseg = 1024; jl = k0 - 1024; }
    else                { mp = m3; nseg = 2048; jl = k0 - 2048; }
    size_t base = (size_t)(b * 1024 + q) * nseg + jl;
    uint32_t bits = 0;
    if (g_mask_is_byte) {
        const uint4* p = (const uint4*)((const unsigned char*)mp + base);
        uint4 a = p[0], c = p[1];
        uint32_t ws[8] = {a.x, a.y, a.z, a.w, c.x, c.y, c.z, c.w};
#pragma unroll
        for (int wi = 0; wi < 8; ++wi)
#pragma unroll
            for (int by = 0; by < 4; ++by)
                if ((ws[wi] >> (8 * by)) & 0xFFu) bits |= 1u << (wi * 4 + by);
    } else {
        const uint4* p = (const uint4*)((const uint32_t*)mp + base);
#pragma unroll
        for (int wi = 0; wi < 8; ++wi) {
            uint4 v = p[wi];
            if (v.x) bits |= 1u << (wi * 4 + 0);
            if (v.y) bits |= 1u << (wi * 4 + 1);
            if (v.z) bits |= 1u << (wi * 4 + 2);
            if (v.w) bits |= 1u << (wi * 4 + 3);
        }
    }
    g_mbits[idx] = bits;
}

// ================= bf16 hi/lo split (pre-pass) =================
struct SplitJobs {
    const float* src[12];
    int nblk[13];
    int off[12];
};
__global__ __launch_bounds__(256) void split_kernel(SplitJobs j, int njobs) {
    int bid = blockIdx.x;
    int ji = 0;
    while (ji + 1 < njobs && bid >= j.nblk[ji + 1]) ++ji;
    int local = bid - j.nblk[ji];
    const float4* src = (const float4*)j.src[ji];
    uint2* dh = (uint2*)(g_h + j.off[ji]);
    uint2* dl = (uint2*)(g_l + j.off[ji]);
    size_t base4 = (size_t)local * 1024;
#pragma unroll
    for (int it = 0; it < 4; ++it) {
        size_t i4 = base4 + it * 256 + threadIdx.x;
        float4 v = src[i4];
        float h0 = bf16_rn(v.x), h1 = bf16_rn(v.y), h2 = bf16_rn(v.z), h3 = bf16_rn(v.w);
        dh[i4] = make_uint2(pkh(h0, h1), pkh(h2, h3));
        dl[i4] = make_uint2(bf2(v.x - h0, v.y - h1), bf2(v.z - h2, v.w - h3));
    }
}

// ================= 3xBF16 HMMA GEMM, term-major mma order =================
#define G_OAL 4608
#define G_OBH 9216
#define G_OBL 11520
#define G_STW 13824
struct GJobs {
    const uint16_t* Ah[7]; const uint16_t* Al[7];
    const uint16_t* Wh[7]; const uint16_t* Wl[7];
    const float* bias[7];  void* C[7];
    int K[7], Mb[7], rowOff[7], bStride[7], mode[7];
    int blk0[8];
    int njobs;
};
// mode: 0 = fp32 out, 1 = tf32-rounded fp32 out, 2 = bf16 out, 4 = bf16 out scaled by EXP2C
__global__ __launch_bounds__(256, 2) void gemm_jobs(GJobs J) {
    extern __shared__ uint32_t smw[];
    int j = 0;
    while (j + 1 < J.njobs && (int)blockIdx.x >= J.blk0[j + 1]) ++j;
    const int lb = blockIdx.x - J.blk0[j];
    const uint16_t* __restrict__ Ah = J.Ah[j];
    const uint16_t* __restrict__ Al = J.Al[j];
    const uint16_t* __restrict__ Wh = J.Wh[j];
    const uint16_t* __restrict__ Wl = J.Wl[j];
    const float* __restrict__ bias = J.bias[j];
    void* Cv = J.C[j];
    const int K = J.K[j], Mb = J.Mb[j], rowOff = J.rowOff[j];
    const int bStride = J.bStride[j], mode = J.mode[j];

    const int tid = threadIdx.x, lane = tid & 31, wid = tid >> 5;
    const int wm = wid & 3, wn = wid >> 2;
    const int lr = lane >> 2, lc = lane & 3;
    const int m0 = (lb >> 3) * 128, n0 = (lb & 7) * 64;
    const int l16 = lane & 15, lh8 = (lane >> 4) << 3;

    float acc[2][4][4];
#pragma unroll
    for (int i = 0; i < 2; ++i)
#pragma unroll
        for (int jj = 0; jj < 4; ++jj)
#pragma unroll
            for (int e = 0; e < 4; ++e) acc[i][jj][e] = 0.f;

    const int nK = K >> 6;
    const uint32_t ub = smem_u32(smw);

#define STAGE(c, s) do { \
    const uint32_t d0 = ub + (s) * G_STW * 4; \
    _Pragma("unroll") \
    for (int it = 0; it < 4; ++it) { \
        int id = it * 256 + tid, row = id >> 3, seg = id & 7; \
        size_t so = (size_t)(m0 + row) * K + (c) * 64 + seg * 8; \
        uint32_t dw = (row * 36 + seg * 4) * 4; \
        CP16(d0 + dw, Ah + so); \
        CP16(d0 + G_OAL * 4 + dw, Al + so); \
    } \
    _Pragma("unroll") \
    for (int it = 0; it < 2; ++it) { \
        int id = it * 256 + tid, row = id >> 3, seg = id & 7; \
        size_t so = (size_t)((c) * 64 + row) * 512 + n0 + seg * 8; \
        uint32_t dw = (row * 36 + seg * 4) * 4; \
        CP16(d0 + G_OBH * 4 + dw, Wh + so); \
        CP16(d0 + G_OBL * 4 + dw, Wl + so); \
    } \
    CP_COMMIT(); \
} while (0)

    STAGE(0, 0);
    for (int c = 0; c < nK; ++c) {
        const int s = c & 1;
        if (c + 1 < nK) { STAGE(c + 1, s ^ 1); CP_WAIT(1); }
        else            { CP_WAIT(0); }
        __syncthreads();
        const uint32_t sb = ub + s * G_STW * 4;
#pragma unroll
        for (int st = 0; st < 4; ++st) {
            const int k0 = st * 16;
            uint32_t ah[2][4], al_[2][4], bh[2][4], bl_[2][4];
#pragma unroll
            for (int mf = 0; mf < 2; ++mf) {
                int row = wm * 32 + mf * 16 + l16;
                uint32_t ad = sb + (row * 36 + ((k0 + lh8) >> 1)) * 4;
                ldsm_x4(ah[mf], ad);
                ldsm_x4(al_[mf], ad + G_OAL * 4);
            }
#pragma unroll
            for (int p = 0; p < 2; ++p) {
                int row = k0 + l16;
                int col = wn * 32 + p * 16 + lh8;
                uint32_t bd = sb + (G_OBH + row * 36 + (col >> 1)) * 4;
                ldsm_x4_t(bh[p], bd);
                ldsm_x4_t(bl_[p], bd + (G_OBL - G_OBH) * 4);
            }
            // term-major issue order: 8-instruction gap between same-accumulator mmas
#pragma unroll
            for (int mf = 0; mf < 2; ++mf)
#pragma unroll
                for (int p = 0; p < 2; ++p) {
                    mma16(acc[mf][p * 2 + 0], ah[mf], &bh[p][0]);
                    mma16(acc[mf][p * 2 + 1], ah[mf], &bh[p][2]);
                }
#pragma unroll
            for (int mf = 0; mf < 2; ++mf)
#pragma unroll
                for (int p = 0; p < 2; ++p) {
                    mma16(acc[mf][p * 2 + 0], ah[mf], &bl_[p][0]);
                    mma16(acc[mf][p * 2 + 1], ah[mf], &bl_[p][2]);
                }
#pragma unroll
            for (int mf = 0; mf < 2; ++mf)
#pragma unroll
                for (int p = 0; p < 2; ++p) {
                    mma16(acc[mf][p * 2 + 0], al_[mf], &bh[p][0]);
                    mma16(acc[mf][p * 2 + 1], al_[mf], &bh[p][2]);
                }
        }
        __syncthreads();
    }
#undef STAGE
#pragma unroll
    for (int mf = 0; mf < 2; ++mf) {
        int r = m0 + wm * 32 + mf * 16 + lr;
        int b0i = r / Mb;
        size_t or0 = (size_t)b0i * bStride + rowOff + (r - b0i * Mb);
        int r2 = r + 8;
        int b1i = r2 / Mb;
        size_t or1 = (size_t)b1i * bStride + rowOff + (r2 - b1i * Mb);
#pragma unroll
        for (int nf = 0; nf < 4; ++nf) {
            int col = n0 + wn * 32 + nf * 8 + 2 * lc;
            float bv0 = bias[col], bv1 = bias[col + 1];
            float v00 = acc[mf][nf][0] + bv0, v01 = acc[mf][nf][1] + bv1;
            float v10 = acc[mf][nf][2] + bv0, v11 = acc[mf][nf][3] + bv1;
            if (mode >= 2) {
                if (mode == 4) { v00 *= EXP2C; v01 *= EXP2C; v10 *= EXP2C; v11 *= EXP2C; }
                uint16_t* Cb = (uint16_t*)Cv;
                *(uint32_t*)(Cb + or0 * 512 + col) = pkh(bf16_rn(v00), bf16_rn(v01));
                *(uint32_t*)(Cb + or1 * 512 + col) = pkh(bf16_rn(v10), bf16_rn(v11));
            } else {
                float* C = (float*)Cv;
                if (mode == 1) {
                    v00 = tf32_rn(v00); v01 = tf32_rn(v01);
                    v10 = tf32_rn(v10); v11 = tf32_rn(v11);
                }
                *(float2*)(C + or0 * 512 + col) = make_float2(v00, v01);
                *(float2*)(C + or1 * 512 + col) = make_float2(v10, v11);
            }
        }
    }
}

// ================= flash attention: 128q x 64k, fragment-major P =================
#define A_QW 0
#define A_KW 4608
#define A_VW 9216
#define A_PW 18432
#define A_MW 27136
#define A_LW 27648
#define A_TOTW 27904
#define AV 72

__global__ __launch_bounds__(256, 2) void attn_mma(
    const uint16_t* __restrict__ qb, const uint16_t* __restrict__ kb,
    const float* __restrict__ vb,
    uint16_t* __restrict__ oh, uint16_t* __restrict__ ol)
{
    extern __shared__ uint32_t smw[];
    float* smf = (float*)smw;
    uint32_t* sM = smw + A_MW;
    float* sP = smf + A_PW;      // fragment-major
    float* sL = smf + A_LW;
    const float4* PF = (const float4*)sP;

    const int tid = threadIdx.x, lane = tid & 31, wid = tid >> 5;
    const int wm = wid & 3, wn = wid >> 2;
    const int lr = lane >> 2, lc = lane & 3;
    const int ln8 = lane & 7;
    const int q0 = blockIdx.x * 128, h = blockIdx.y, b = blockIdx.z;

    const uint16_t* Qg = qb + ((size_t)(b * 1024 + q0)) * 512 + h * 64;
    const uint16_t* Kg = kb + ((size_t)(b * 4096)) * 512 + h * 64;
    const float*    Vg = vb + ((size_t)(b * 4096)) * 512 + h * 64;
    const uint32_t* mbase = g_mbits + ((size_t)(b * 1024 + q0)) * 128;
    const uint32_t ubase = smem_u32(smw);
    const uint32_t uQ = ubase + A_QW * 4, uK = ubase + A_KW * 4;
    const uint32_t uV = ubase + A_VW * 4, uM = ubase + A_MW * 4;

#pragma unroll
    for (int it = 0; it < 4; ++it) {
        int id = it * 256 + tid, row = id >> 3, seg = id & 7;
        CP16(uQ + (row * 36 + seg * 4) * 4, Qg + (size_t)row * 512 + seg * 8);
    }
#pragma unroll
    for (int it = 0; it < 2; ++it) {
        int id = it * 256 + tid, row = id >> 3, seg = id & 7;
        CP16(uK + (row * 36 + seg * 4) * 4, Kg + (size_t)row * 512 + seg * 8);
    }
#pragma unroll
    for (int it = 0; it < 4; ++it) {
        int id = it * 256 + tid, row = id >> 4, seg = id & 15;
        CP16(uV + (row * AV + seg * 4) * 4, Vg + (size_t)row * 512 + seg * 4);
    }
    if (tid < 128) CP8(uM + tid * 8, (const char*)(mbase + (size_t)tid * 128));
    CP_COMMIT();
    CP_WAIT(0);
    __syncthreads();

    float o[2][4][4];
    float l_acc[2][2];
#pragma unroll
    for (int i = 0; i < 2; ++i) {
        l_acc[i][0] = 0.f; l_acc[i][1] = 0.f;
#pragma unroll
        for (int jj = 0; jj < 4; ++jj)
#pragma unroll
            for (int e = 0; e < 4; ++e) o[i][jj][e] = 0.f;
    }

    for (int t = 0; t < 64; ++t) {
        const int s = t & 1;
        if (t > 0) { CP_WAIT(0); __syncthreads(); }

        if (t < 63) {
            const uint16_t* Kn = Kg + (size_t)(t + 1) * 64 * 512;
            const float* Vn = Vg + (size_t)(t + 1) * 64 * 512;
            const uint32_t dK = uK + (s ^ 1) * 2304 * 4;
            const uint32_t dV = uV + (s ^ 1) * 64 * AV * 4;
#pragma unroll
            for (int it = 0; it < 2; ++it) {
                int id = it * 256 + tid, row = id >> 3, seg = id & 7;
                CP16(dK + (row * 36 + seg * 4) * 4, Kn + (size_t)row * 512 + seg * 8);
            }
#pragma unroll
            for (int it = 0; it < 4; ++it) {
                int id = it * 256 + tid, row = id >> 4, seg = id & 15;
                CP16(dV + (row * AV + seg * 4) * 4, Vn + (size_t)row * 512 + seg * 4);
            }
            if (tid < 128)
                CP8(uM + (s ^ 1) * 1024 + tid * 8,
                    (const char*)(mbase + (size_t)tid * 128 + (t + 1) * 2));
            CP_COMMIT();
        }

        // ---- S' = (Q*EXP2C) K^T ----
        const uint32_t uKs = uK + s * 2304 * 4;
        float sv[2][4][4];
#pragma unroll
        for (int i = 0; i < 2; ++i)
#pragma unroll
            for (int jj = 0; jj < 4; ++jj)
#pragma unroll
                for (int e = 0; e < 4; ++e) sv[i][jj][e] = 0.f;
#pragma unroll
        for (int ks = 0; ks < 4; ++ks) {
            int kcb = ks * 16 + ((lane >> 3) & 1) * 8;
            int nrow = wn * 32 + (lane >> 4) * 8 + ln8;
            uint32_t bk0[4], bk1[4];
            ldsm_x4(bk0, uKs + (nrow * 36 + (kcb >> 1)) * 4);
            ldsm_x4(bk1, uKs + ((nrow + 16) * 36 + (kcb >> 1)) * 4);
#pragma unroll
            for (int mf = 0; mf < 2; ++mf) {
                int qrow = wm * 32 + mf * 16 + ((lane >> 3) & 1) * 8 + ln8;
                int kc = ks * 16 + (lane >> 4) * 8;
                uint32_t aq[4];
                ldsm_x4(aq, uQ + (qrow * 36 + (kc >> 1)) * 4);
                mma16(sv[mf][0], aq, &bk0[0]);
                mma16(sv[mf][1], aq, &bk0[2]);
                mma16(sv[mf][2], aq, &bk1[0]);
                mma16(sv[mf][3], aq, &bk1[2]);
            }
        }

        // ---- masked no-max softmax + fragment-major P write ----
#pragma unroll
        for (int mf = 0; mf < 2; ++mf)
#pragma unroll
            for (int u = 0; u < 2; ++u) {
                int row = wm * 32 + mf * 16 + lr + u * 8;
                uint32_t mw = sM[s * 256 + row * 2 + wn];
                float rs = 0.f;
#pragma unroll
                for (int nf = 0; nf < 4; ++nf) {
#pragma unroll
                    for (int q2 = 0; q2 < 2; ++q2) {
                        int cr = u * 2 + q2;
                        int cl = nf * 8 + 2 * lc + q2;
                        float p = tf32_cvt(ex2f(sv[mf][nf][cr]));
                        p = ((mw >> cl) & 1u) ? p : 0.f;
                        rs += p;
                        sv[mf][nf][cr] = p;
                    }
                }
                l_acc[mf][u] += rs;
                int gbase = (((wm * 2 + mf) * 8 + wn * 4) * 8 + lr) * 16 + u + 2 * (lc >> 1);
                int c0 = (lc & 1) * 8;
#pragma unroll
                for (int nf = 0; nf < 4; ++nf) {
                    sP[gbase + nf * 128 + c0]     = sv[mf][nf][u * 2];
                    sP[gbase + nf * 128 + c0 + 4] = sv[mf][nf][u * 2 + 1];
                }
            }
        __syncthreads();

        // ---- O += P @ V ----
        const uint32_t* sVu = smw + A_VW + s * 64 * AV;
#pragma unroll
        for (int ks = 0; ks < 8; ++ks) {
            const int kb0 = ks * 8;
            uint32_t bv[4][2];
#pragma unroll
            for (int nf = 0; nf < 4; ++nf) {
                int drow = wn * 32 + nf * 8 + lr;
                bv[nf][0] = sVu[(kb0 + lc) * AV + drow];
                bv[nf][1] = sVu[(kb0 + 4 + lc) * AV + drow];
            }
#pragma unroll
            for (int mf = 0; mf < 2; ++mf) {
                float4 av = PF[(((wm * 2 + mf) * 8 + ks) * 8 + lr) * 4 + lc];
                uint32_t ap[4] = {__float_as_uint(av.x), __float_as_uint(av.y),
                                  __float_as_uint(av.z), __float_as_uint(av.w)};
#pragma unroll
                for (int nf = 0; nf < 4; ++nf) mma8(o[mf][nf], ap, bv[nf]);
            }
        }
    }

#pragma unroll
    for (int mf = 0; mf < 2; ++mf)
#pragma unroll
        for (int u = 0; u < 2; ++u) {
            float v = l_acc[mf][u];
            v += __shfl_xor_sync(0xffffffffu, v, 1);
            v += __shfl_xor_sync(0xffffffffu, v, 2);
            l_acc[mf][u] = v;
        }
    if (lc == 0) {
#pragma unroll
        for (int mf = 0; mf < 2; ++mf)
#pragma unroll
            for (int u = 0; u < 2; ++u)
                sL[wn * 128 + wm * 32 + mf * 16 + lr + u * 8] = l_acc[mf][u];
    }
    __syncthreads();

    uint16_t* Oh = oh + ((size_t)(b * 1024 + q0)) * 512 + h * 64;
    uint16_t* Ol = ol + ((size_t)(b * 1024 + q0)) * 512 + h * 64;
#pragma unroll
    for (int mf = 0; mf < 2; ++mf)
#pragma unroll
        for (int u = 0; u < 2; ++u) {
            int row = wm * 32 + mf * 16 + lr + u * 8;
            float linv = 1.f / (sL[row] + sL[128 + row]);
#pragma unroll
            for (int nf = 0; nf < 4; ++nf) {
                int col = wn * 32 + nf * 8 + 2 * lc;
                float v0 = o[mf][nf][u * 2] * linv;
                float v1 = o[mf][nf][u * 2 + 1] * linv;
                float h0 = bf16_rn(v0), h1 = bf16_rn(v1);
                *(uint32_t*)(Oh + (size_t)row * 512 + col) = pkh(h0, h1);
                *(uint32_t*)(Ol + (size_t)row * 512 + col) = bf2(v0 - h0, v1 - h1);
            }
        }
}

// ================= launcher =================
extern "C" void kernel_launch(void* const* d_in, const int* in_sizes, int n_in,
                              void* d_out, int out_size) {
    const float* x        = (const float*)d_in[0];
    const float* context  = (const float*)d_in[1];
    const float* context2 = (const float*)d_in[2];
    const float* context3 = (const float*)d_in[3];
    const void*  mask1 = d_in[4];
    const void*  mask2 = d_in[5];
    const void*  mask3 = d_in[6];
    const float* bq  = (const float*)d_in[8];
    const float* bk1 = (const float*)d_in[10];
    const float* bv1 = (const float*)d_in[12];
    const float* bk2 = (const float*)d_in[14];
    const float* bv2 = (const float*)d_in[16];
    const float* bk3 = (const float*)d_in[18];
    const float* bv3 = (const float*)d_in[20];
    const float* Wo  = (const float*)d_in[21];
    const float* bo  = (const float*)d_in[22];
    float* out = (float*)d_out;

    uint16_t *hp, *lp, *qbp, *kbp;
    float *vp;
    cudaGetSymbolAddress((void**)&hp,  g_h);
    cudaGetSymbolAddress((void**)&lp,  g_l);
    cudaGetSymbolAddress((void**)&qbp, g_qb);
    cudaGetSymbolAddress((void**)&kbp, g_kb);
    cudaGetSymbolAddress((void**)&vp,  g_v);

    const int smem_gemm = 2 * G_STW * 4;
    const int smem_attn = A_TOTW * 4;
    static bool once = false;
    static cudaStream_t s2;
    static cudaEvent_t ev1, ev2;
    if (!once) {
        cudaFuncSetAttribute(gemm_jobs, cudaFuncAttributeMaxDynamicSharedMemorySize, smem_gemm);
        cudaFuncSetAttribute(attn_mma, cudaFuncAttributeMaxDynamicSharedMemorySize, smem_attn);
        cudaStreamCreateWithFlags(&s2, cudaStreamNonBlocking);
        cudaEventCreateWithFlags(&ev1, cudaEventDisableTiming);
        cudaEventCreateWithFlags(&ev2, cudaEventDisableTiming);
        once = true;
    }

    cudaEventRecord(ev1, 0);
    cudaStreamWaitEvent(s2, ev1, 0);
    detect_mask_kernel<<<1, 256, 0, s2>>>((const unsigned char*)mask1);
    pack_mask_kernel<<<2048, 256, 0, s2>>>(mask1, mask2, mask3);
    cudaEventRecord(ev2, s2);

    {
        SplitJobs js;
        const float* srcs[12] = {x, context, context2, context3,
                                 (const float*)d_in[7], (const float*)d_in[9],
                                 (const float*)d_in[11], (const float*)d_in[13],
                                 (const float*)d_in[15], (const float*)d_in[17],
                                 (const float*)d_in[19], Wo};
        int offs[12] = {OFF_X, OFF_C1, OFF_C2, OFF_C3,
                        OFF_WQ, OFF_WK1, OFF_WV1, OFF_WK2, OFF_WV2,
                        OFF_WK3, OFF_WV3, OFF_WO};
        int cnts[12] = {512, 512, 768, 512, 64, 64, 64, 96, 96, 32, 32, 64};
        int cum = 0;
        for (int i = 0; i < 12; ++i) {
            js.src[i] = srcs[i]; js.off[i] = offs[i];
            js.nblk[i] = cum; cum += cnts[i];
        }
        js.nblk[12] = cum;
        split_kernel<<<cum, 256>>>(js, 12);
    }

    {
        GJobs J;
        int aoffs[7]  = {OFF_X, OFF_C1, OFF_C2, OFF_C3, OFF_C1, OFF_C2, OFF_C3};
        int woffs[7]  = {OFF_WQ, OFF_WK1, OFF_WK2, OFF_WK3, OFF_WV1, OFF_WV2, OFF_WV3};
        const float* biases[7] = {bq, bk1, bk2, bk3, bv1, bv2, bv3};
        void* Cs[7]   = {qbp, kbp, kbp, kbp, vp, vp, vp};
        int Ks[7]     = {512, 512, 768, 256, 512, 768, 256};
        int Mbs[7]    = {1024, 1024, 1024, 2048, 1024, 1024, 2048};
        int ros[7]    = {0, 0, 1024, 2048, 0, 1024, 2048};
        int bss[7]    = {1024, 4096, 4096, 4096, 4096, 4096, 4096};
        int modes[7]  = {4, 2, 2, 2, 1, 1, 1};
        int blks[7]   = {256, 256, 256, 512, 256, 256, 512};
        int cum = 0;
        for (int i = 0; i < 7; ++i) {
            J.Ah[i] = hp + aoffs[i]; J.Al[i] = lp + aoffs[i];
            J.Wh[i] = hp + woffs[i]; J.Wl[i] = lp + woffs[i];
            J.bias[i] = biases[i]; J.C[i] = Cs[i];
            J.K[i] = Ks[i]; J.Mb[i] = Mbs[i]; J.rowOff[i] = ros[i];
            J.bStride[i] = bss[i]; J.mode[i] = modes[i];
            J.blk0[i] = cum; cum += blks[i];
        }
        J.blk0[7] = cum; J.njobs = 7;
        gemm_jobs<<<cum, 256, smem_gemm>>>(J);
    }

    cudaStreamWaitEvent(0, ev2, 0);

    attn_mma<<<dim3(8, 8, 4), 256, smem_attn>>>(qbp, kbp, vp, hp + OFF_AO, lp + OFF_AO);

    {
        GJobs J;
        J.Ah[0] = hp + OFF_AO; J.Al[0] = lp + OFF_AO;
        J.Wh[0] = hp + OFF_WO; J.Wl[0] = lp + OFF_WO;
        J.bias[0] = bo; J.C[0] = out;
        J.K[0] = 512; J.Mb[0] = 1024; J.rowOff[0] = 0;
        J.bStride[0] = 1024; J.mode[0] = 0;
        J.blk0[0] = 0; J.blk0[1] = 256; J.njobs = 1;
        gemm_jobs<<<256, 256, smem_gemm>>>(J);
    }
}

// round 14
// speedup vs baseline: 1.0157x; 1.0156x over previous
#include <cuda_runtime.h>
#include <cstdint>

#define EXP2C 0.1803368801111204f   /* (1/8) * log2(e) */

// ================= pools / scratch =================
#define OFF_X   0
#define OFF_C1  2097152
#define OFF_C2  4194304
#define OFF_C3  7340032
#define OFF_AO  9437184
#define OFF_WQ  11534336
#define OFF_WK1 11796480
#define OFF_WV1 12058624
#define OFF_WK2 12320768
#define OFF_WV2 12713984
#define OFF_WK3 13107200
#define OFF_WV3 13238272
#define OFF_WO  13369344
#define POOL_N  13631488

__device__ uint16_t g_h[POOL_N];
__device__ uint16_t g_l[POOL_N];
__device__ uint16_t g_qb[4 * 1024 * 512];
__device__ uint16_t g_kb[4 * 4096 * 512];
__device__ float    g_v[4 * 4096 * 512];
__device__ uint32_t g_mbits[4 * 1024 * 128];
__device__ int      g_mask_is_byte;

// ================= helpers =================
__device__ __forceinline__ uint32_t smem_u32(const void* p) {
    uint32_t a;
    asm("{ .reg .u64 t; cvta.to.shared.u64 t, %1; cvt.u32.u64 %0, t; }" : "=r"(a) : "l"(p));
    return a;
}
#define CP16(dst, src) \
    asm volatile("cp.async.cg.shared.global [%0], [%1], 16;" :: "r"(dst), "l"(src))
#define CP8(dst, src) \
    asm volatile("cp.async.ca.shared.global [%0], [%1], 8;" :: "r"(dst), "l"(src))
#define CP_COMMIT() asm volatile("cp.async.commit_group;" ::: "memory")
#define CP_WAIT(n)  asm volatile("cp.async.wait_group %0;" :: "n"(n) : "memory")
#define PAIR_BAR(id) \
    asm volatile("bar.sync %0, 64;" :: "r"(id) : "memory")

__device__ __forceinline__ float tf32_rn(float x) {
    return __uint_as_float((__float_as_uint(x) + 0x1000u) & 0xFFFFE000u);
}
__device__ __forceinline__ float tf32_cvt(float x) {
    uint32_t r;
    asm("cvt.rna.tf32.f32 %0, %1;" : "=r"(r) : "f"(x));
    return __uint_as_float(r);
}
__device__ __forceinline__ float bf16_rn(float x) {
    uint32_t u = __float_as_uint(x);
    u += 0x7FFFu + ((u >> 16) & 1u);
    return __uint_as_float(u & 0xFFFF0000u);
}
__device__ __forceinline__ uint32_t pkh(float a, float b) {
    return (__float_as_uint(b) & 0xFFFF0000u) | (__float_as_uint(a) >> 16);
}
__device__ __forceinline__ uint32_t bf2(float a, float b) {
    uint32_t r;
    asm("cvt.rn.bf16x2.f32 %0, %1, %2;" : "=r"(r) : "f"(b), "f"(a));
    return r;
}
__device__ __forceinline__ float ex2f(float y) {
    float r;
    asm("ex2.approx.f32 %0, %1;" : "=f"(r) : "f"(y));
    return r;
}
__device__ __forceinline__ void mma8(float* c, const uint32_t* a, const uint32_t* b) {
    asm volatile("mma.sync.aligned.m16n8k8.row.col.f32.tf32.tf32.f32 "
        "{%0,%1,%2,%3},{%4,%5,%6,%7},{%8,%9},{%0,%1,%2,%3};"
        : "+f"(c[0]), "+f"(c[1]), "+f"(c[2]), "+f"(c[3])
        : "r"(a[0]), "r"(a[1]), "r"(a[2]), "r"(a[3]), "r"(b[0]), "r"(b[1]));
}
__device__ __forceinline__ void mma16(float* c, const uint32_t* a, const uint32_t* b) {
    asm volatile("mma.sync.aligned.m16n8k16.row.col.f32.bf16.bf16.f32 "
        "{%0,%1,%2,%3},{%4,%5,%6,%7},{%8,%9},{%0,%1,%2,%3};"
        : "+f"(c[0]), "+f"(c[1]), "+f"(c[2]), "+f"(c[3])
        : "r"(a[0]), "r"(a[1]), "r"(a[2]), "r"(a[3]), "r"(b[0]), "r"(b[1]));
}
__device__ __forceinline__ void ldsm_x4(uint32_t* r, uint32_t addr) {
    asm volatile("ldmatrix.sync.aligned.m8n8.x4.shared.b16 {%0,%1,%2,%3}, [%4];"
        : "=r"(r[0]), "=r"(r[1]), "=r"(r[2]), "=r"(r[3]) : "r"(addr));
}
__device__ __forceinline__ void ldsm_x4_t(uint32_t* r, uint32_t addr) {
    asm volatile("ldmatrix.sync.aligned.m8n8.x4.trans.shared.b16 {%0,%1,%2,%3}, [%4];"
        : "=r"(r[0]), "=r"(r[1]), "=r"(r[2]), "=r"(r[3]) : "r"(addr));
}

// ================= mask detect + bit-pack =================
__global__ void detect_mask_kernel(const unsigned char* __restrict__ m) {
    __shared__ int any;
    if (threadIdx.x == 0) any = 0;
    __syncthreads();
    int found = 0;
    for (int i = threadIdx.x; i < 4096; i += blockDim.x)
        if ((i & 3) == 1 && m[i]) found = 1;
    if (found) atomicOr(&any, 1);
    __syncthreads();
    if (threadIdx.x == 0) g_mask_is_byte = any;
}

__global__ void pack_mask_kernel(const void* __restrict__ m1, const void* __restrict__ m2,
                                 const void* __restrict__ m3) {
    int idx = blockIdx.x * blockDim.x + threadIdx.x;
    if (idx >= 4 * 1024 * 128) return;
    int w = idx & 127, q = (idx >> 7) & 1023, b = idx >> 17;
    int k0 = w * 32;
    const void* mp; int nseg, jl;
    if (k0 < 1024)      { mp = m1; nseg = 1024; jl = k0; }
    else if (k0 < 2048) { mp = m2; nseg = 1024; jl = k0 - 1024; }
    else                { mp = m3; nseg = 2048; jl = k0 - 2048; }
    size_t base = (size_t)(b * 1024 + q) * nseg + jl;
    uint32_t bits = 0;
    if (g_mask_is_byte) {
        const uint4* p = (const uint4*)((const unsigned char*)mp + base);
        uint4 a = p[0], c = p[1];
        uint32_t ws[8] = {a.x, a.y, a.z, a.w, c.x, c.y, c.z, c.w};
#pragma unroll
        for (int wi = 0; wi < 8; ++wi)
#pragma unroll
            for (int by = 0; by < 4; ++by)
                if ((ws[wi] >> (8 * by)) & 0xFFu) bits |= 1u << (wi * 4 + by);
    } else {
        const uint4* p = (const uint4*)((const uint32_t*)mp + base);
#pragma unroll
        for (int wi = 0; wi < 8; ++wi) {
            uint4 v = p[wi];
            if (v.x) bits |= 1u << (wi * 4 + 0);
            if (v.y) bits |= 1u << (wi * 4 + 1);
            if (v.z) bits |= 1u << (wi * 4 + 2);
            if (v.w) bits |= 1u << (wi * 4 + 3);
        }
    }
    g_mbits[idx] = bits;
}

// ================= bf16 hi/lo split (pre-pass) =================
struct SplitJobs {
    const float* src[12];
    int nblk[13];
    int off[12];
};
__global__ __launch_bounds__(256) void split_kernel(SplitJobs j, int njobs) {
    int bid = blockIdx.x;
    int ji = 0;
    while (ji + 1 < njobs && bid >= j.nblk[ji + 1]) ++ji;
    int local = bid - j.nblk[ji];
    const float4* src = (const float4*)j.src[ji];
    uint2* dh = (uint2*)(g_h + j.off[ji]);
    uint2* dl = (uint2*)(g_l + j.off[ji]);
    size_t base4 = (size_t)local * 1024;
#pragma unroll
    for (int it = 0; it < 4; ++it) {
        size_t i4 = base4 + it * 256 + threadIdx.x;
        float4 v = src[i4];
        float h0 = bf16_rn(v.x), h1 = bf16_rn(v.y), h2 = bf16_rn(v.z), h3 = bf16_rn(v.w);
        dh[i4] = make_uint2(pkh(h0, h1), pkh(h2, h3));
        dl[i4] = make_uint2(bf2(v.x - h0, v.y - h1), bf2(v.z - h2, v.w - h3));
    }
}

// ================= 3xBF16 HMMA GEMM, job-table, cp.async 2-stage =================
#define G_OAL 4608
#define G_OBH 9216
#define G_OBL 11520
#define G_STW 13824
struct GJobs {
    const uint16_t* Ah[7]; const uint16_t* Al[7];
    const uint16_t* Wh[7]; const uint16_t* Wl[7];
    const float* bias[7];  void* C[7];
    int K[7], Mb[7], rowOff[7], bStride[7], mode[7];
    int blk0[8];
    int njobs;
};
// mode: 0 = fp32 out, 1 = tf32-rounded fp32 out, 2 = bf16 out, 4 = bf16 out scaled by EXP2C
__global__ __launch_bounds__(256, 2) void gemm_jobs(GJobs J) {
    extern __shared__ uint32_t smw[];
    int j = 0;
    while (j + 1 < J.njobs && (int)blockIdx.x >= J.blk0[j + 1]) ++j;
    const int lb = blockIdx.x - J.blk0[j];
    const uint16_t* __restrict__ Ah = J.Ah[j];
    const uint16_t* __restrict__ Al = J.Al[j];
    const uint16_t* __restrict__ Wh = J.Wh[j];
    const uint16_t* __restrict__ Wl = J.Wl[j];
    const float* __restrict__ bias = J.bias[j];
    void* Cv = J.C[j];
    const int K = J.K[j], Mb = J.Mb[j], rowOff = J.rowOff[j];
    const int bStride = J.bStride[j], mode = J.mode[j];

    const int tid = threadIdx.x, lane = tid & 31, wid = tid >> 5;
    const int wm = wid & 3, wn = wid >> 2;
    const int lr = lane >> 2, lc = lane & 3;
    const int m0 = (lb >> 3) * 128, n0 = (lb & 7) * 64;
    const int l16 = lane & 15, lh8 = (lane >> 4) << 3;

    float acc[2][4][4];
#pragma unroll
    for (int i = 0; i < 2; ++i)
#pragma unroll
        for (int jj = 0; jj < 4; ++jj)
#pragma unroll
            for (int e = 0; e < 4; ++e) acc[i][jj][e] = 0.f;

    const int nK = K >> 6;
    const uint32_t ub = smem_u32(smw);

#define STAGE(c, s) do { \
    const uint32_t d0 = ub + (s) * G_STW * 4; \
    _Pragma("unroll") \
    for (int it = 0; it < 4; ++it) { \
        int id = it * 256 + tid, row = id >> 3, seg = id & 7; \
        size_t so = (size_t)(m0 + row) * K + (c) * 64 + seg * 8; \
        uint32_t dw = (row * 36 + seg * 4) * 4; \
        CP16(d0 + dw, Ah + so); \
        CP16(d0 + G_OAL * 4 + dw, Al + so); \
    } \
    _Pragma("unroll") \
    for (int it = 0; it < 2; ++it) { \
        int id = it * 256 + tid, row = id >> 3, seg = id & 7; \
        size_t so = (size_t)((c) * 64 + row) * 512 + n0 + seg * 8; \
        uint32_t dw = (row * 36 + seg * 4) * 4; \
        CP16(d0 + G_OBH * 4 + dw, Wh + so); \
        CP16(d0 + G_OBL * 4 + dw, Wl + so); \
    } \
    CP_COMMIT(); \
} while (0)

    STAGE(0, 0);
    for (int c = 0; c < nK; ++c) {
        const int s = c & 1;
        if (c + 1 < nK) { STAGE(c + 1, s ^ 1); CP_WAIT(1); }
        else            { CP_WAIT(0); }
        __syncthreads();
        const uint32_t sb = ub + s * G_STW * 4;
#pragma unroll
        for (int st = 0; st < 4; ++st) {
            const int k0 = st * 16;
            uint32_t ah[2][4], al_[2][4], bh[2][4], bl_[2][4];
#pragma unroll
            for (int mf = 0; mf < 2; ++mf) {
                int row = wm * 32 + mf * 16 + l16;
                uint32_t ad = sb + (row * 36 + ((k0 + lh8) >> 1)) * 4;
                ldsm_x4(ah[mf], ad);
                ldsm_x4(al_[mf], ad + G_OAL * 4);
            }
#pragma unroll
            for (int p = 0; p < 2; ++p) {
                int row = k0 + l16;
                int col = wn * 32 + p * 16 + lh8;
                uint32_t bd = sb + (G_OBH + row * 36 + (col >> 1)) * 4;
                ldsm_x4_t(bh[p], bd);
                ldsm_x4_t(bl_[p], bd + (G_OBL - G_OBH) * 4);
            }
#pragma unroll
            for (int mf = 0; mf < 2; ++mf)
#pragma unroll
                for (int p = 0; p < 2; ++p) {
                    mma16(acc[mf][p * 2 + 0], ah[mf], &bh[p][0]);
                    mma16(acc[mf][p * 2 + 1], ah[mf], &bh[p][2]);
                }
#pragma unroll
            for (int mf = 0; mf < 2; ++mf)
#pragma unroll
                for (int p = 0; p < 2; ++p) {
                    mma16(acc[mf][p * 2 + 0], ah[mf], &bl_[p][0]);
                    mma16(acc[mf][p * 2 + 1], ah[mf], &bl_[p][2]);
                }
#pragma unroll
            for (int mf = 0; mf < 2; ++mf)
#pragma unroll
                for (int p = 0; p < 2; ++p) {
                    mma16(acc[mf][p * 2 + 0], al_[mf], &bh[p][0]);
                    mma16(acc[mf][p * 2 + 1], al_[mf], &bh[p][2]);
                }
        }
        __syncthreads();
    }
#undef STAGE
#pragma unroll
    for (int mf = 0; mf < 2; ++mf) {
        int r = m0 + wm * 32 + mf * 16 + lr;
        int b0i = r / Mb;
        size_t or0 = (size_t)b0i * bStride + rowOff + (r - b0i * Mb);
        int r2 = r + 8;
        int b1i = r2 / Mb;
        size_t or1 = (size_t)b1i * bStride + rowOff + (r2 - b1i * Mb);
#pragma unroll
        for (int nf = 0; nf < 4; ++nf) {
            int col = n0 + wn * 32 + nf * 8 + 2 * lc;
            float bv0 = bias[col], bv1 = bias[col + 1];
            float v00 = acc[mf][nf][0] + bv0, v01 = acc[mf][nf][1] + bv1;
            float v10 = acc[mf][nf][2] + bv0, v11 = acc[mf][nf][3] + bv1;
            if (mode >= 2) {
                if (mode == 4) { v00 *= EXP2C; v01 *= EXP2C; v10 *= EXP2C; v11 *= EXP2C; }
                uint16_t* Cb = (uint16_t*)Cv;
                *(uint32_t*)(Cb + or0 * 512 + col) = pkh(bf16_rn(v00), bf16_rn(v01));
                *(uint32_t*)(Cb + or1 * 512 + col) = pkh(bf16_rn(v10), bf16_rn(v11));
            } else {
                float* C = (float*)Cv;
                if (mode == 1) {
                    v00 = tf32_rn(v00); v01 = tf32_rn(v01);
                    v10 = tf32_rn(v10); v11 = tf32_rn(v11);
                }
                *(float2*)(C + or0 * 512 + col) = make_float2(v00, v01);
                *(float2*)(C + or1 * 512 + col) = make_float2(v10, v11);
            }
        }
    }
}

// ================= flash attention: pair-barrier phase overlap =================
// 8 warps as 4 pairs {wm, wm+4}. P exchange is pair-local (bar.sync 1+wm, 64);
// only K/V/M buffer recycling uses the full-CTA barrier (1 per tile).
#define A_QW 0
#define A_KW 4608
#define A_VW 9216
#define A_PW 18432
#define A_MW 27136
#define A_LW 27648
#define A_TOTW 27904
#define AV 72

__global__ __launch_bounds__(256, 2) void attn_mma(
    const uint16_t* __restrict__ qb, const uint16_t* __restrict__ kb,
    const float* __restrict__ vb,
    uint16_t* __restrict__ oh, uint16_t* __restrict__ ol)
{
    extern __shared__ uint32_t smw[];
    float* smf = (float*)smw;
    uint32_t* sM = smw + A_MW;
    float* sP = smf + A_PW;      // fragment-major
    float* sL = smf + A_LW;
    const float4* PF = (const float4*)sP;

    const int tid = threadIdx.x, lane = tid & 31, wid = tid >> 5;
    const int wm = wid & 3, wn = wid >> 2;
    const int lr = lane >> 2, lc = lane & 3;
    const int ln8 = lane & 7;
    const int pair_bar_id = 1 + wm;
    const int q0 = blockIdx.x * 128, h = blockIdx.y, b = blockIdx.z;

    const uint16_t* Qg = qb + ((size_t)(b * 1024 + q0)) * 512 + h * 64;
    const uint16_t* Kg = kb + ((size_t)(b * 4096)) * 512 + h * 64;
    const float*    Vg = vb + ((size_t)(b * 4096)) * 512 + h * 64;
    const uint32_t* mbase = g_mbits + ((size_t)(b * 1024 + q0)) * 128;
    const uint32_t ubase = smem_u32(smw);
    const uint32_t uQ = ubase + A_QW * 4, uK = ubase + A_KW * 4;
    const uint32_t uV = ubase + A_VW * 4, uM = ubase + A_MW * 4;

#pragma unroll
    for (int it = 0; it < 4; ++it) {
        int id = it * 256 + tid, row = id >> 3, seg = id & 7;
        CP16(uQ + (row * 36 + seg * 4) * 4, Qg + (size_t)row * 512 + seg * 8);
    }
#pragma unroll
    for (int it = 0; it < 2; ++it) {
        int id = it * 256 + tid, row = id >> 3, seg = id & 7;
        CP16(uK + (row * 36 + seg * 4) * 4, Kg + (size_t)row * 512 + seg * 8);
    }
#pragma unroll
    for (int it = 0; it < 4; ++it) {
        int id = it * 256 + tid, row = id >> 4, seg = id & 15;
        CP16(uV + (row * AV + seg * 4) * 4, Vg + (size_t)row * 512 + seg * 4);
    }
    if (tid < 128) CP8(uM + tid * 8, (const char*)(mbase + (size_t)tid * 128));
    CP_COMMIT();
    CP_WAIT(0);
    __syncthreads();

    float o[2][4][4];
    float l_acc[2][2];
#pragma unroll
    for (int i = 0; i < 2; ++i) {
        l_acc[i][0] = 0.f; l_acc[i][1] = 0.f;
#pragma unroll
        for (int jj = 0; jj < 4; ++jj)
#pragma unroll
            for (int e = 0; e < 4; ++e) o[i][jj][e] = 0.f;
    }

    for (int t = 0; t < 64; ++t) {
        const int s = t & 1;
        if (t > 0) { CP_WAIT(0); __syncthreads(); }   // only full-CTA sync per tile

        if (t < 63) {
            const uint16_t* Kn = Kg + (size_t)(t + 1) * 64 * 512;
            const float* Vn = Vg + (size_t)(t + 1) * 64 * 512;
            const uint32_t dK = uK + (s ^ 1) * 2304 * 4;
            const uint32_t dV = uV + (s ^ 1) * 64 * AV * 4;
#pragma unroll
            for (int it = 0; it < 2; ++it) {
                int id = it * 256 + tid, row = id >> 3, seg = id & 7;
                CP16(dK + (row * 36 + seg * 4) * 4, Kn + (size_t)row * 512 + seg * 8);
            }
#pragma unroll
            for (int it = 0; it < 4; ++it) {
                int id = it * 256 + tid, row = id >> 4, seg = id & 15;
                CP16(dV + (row * AV + seg * 4) * 4, Vn + (size_t)row * 512 + seg * 4);
            }
            if (tid < 128)
                CP8(uM + (s ^ 1) * 1024 + tid * 8,
                    (const char*)(mbase + (size_t)tid * 128 + (t + 1) * 2));
            CP_COMMIT();
        }

        // ---- S' = (Q*EXP2C) K^T ----
        const uint32_t uKs = uK + s * 2304 * 4;
        float sv[2][4][4];
#pragma unroll
        for (int i = 0; i < 2; ++i)
#pragma unroll
            for (int jj = 0; jj < 4; ++jj)
#pragma unroll
                for (int e = 0; e < 4; ++e) sv[i][jj][e] = 0.f;
#pragma unroll
        for (int ks = 0; ks < 4; ++ks) {
            int kcb = ks * 16 + ((lane >> 3) & 1) * 8;
            int nrow = wn * 32 + (lane >> 4) * 8 + ln8;
            uint32_t bk0[4], bk1[4];
            ldsm_x4(bk0, uKs + (nrow * 36 + (kcb >> 1)) * 4);
            ldsm_x4(bk1, uKs + ((nrow + 16) * 36 + (kcb >> 1)) * 4);
#pragma unroll
            for (int mf = 0; mf < 2; ++mf) {
                int qrow = wm * 32 + mf * 16 + ((lane >> 3) & 1) * 8 + ln8;
                int kc = ks * 16 + (lane >> 4) * 8;
                uint32_t aq[4];
                ldsm_x4(aq, uQ + (qrow * 36 + (kc >> 1)) * 4);
                mma16(sv[mf][0], aq, &bk0[0]);
                mma16(sv[mf][1], aq, &bk0[2]);
                mma16(sv[mf][2], aq, &bk1[0]);
                mma16(sv[mf][3], aq, &bk1[2]);
            }
        }

        // ---- masked no-max softmax + fragment-major P write ----
#pragma unroll
        for (int mf = 0; mf < 2; ++mf)
#pragma unroll
            for (int u = 0; u < 2; ++u) {
                int row = wm * 32 + mf * 16 + lr + u * 8;
                uint32_t mw = sM[s * 256 + row * 2 + wn];
                float rs = 0.f;
#pragma unroll
                for (int nf = 0; nf < 4; ++nf) {
#pragma unroll
                    for (int q2 = 0; q2 < 2; ++q2) {
                        int cr = u * 2 + q2;
                        int cl = nf * 8 + 2 * lc + q2;
                        float p = tf32_cvt(ex2f(sv[mf][nf][cr]));
                        p = ((mw >> cl) & 1u) ? p : 0.f;
                        rs += p;
                        sv[mf][nf][cr] = p;
                    }
                }
                l_acc[mf][u] += rs;
                int gbase = (((wm * 2 + mf) * 8 + wn * 4) * 8 + lr) * 16 + u + 2 * (lc >> 1);
                int c0 = (lc & 1) * 8;
#pragma unroll
                for (int nf = 0; nf < 4; ++nf) {
                    sP[gbase + nf * 128 + c0]     = sv[mf][nf][u * 2];
                    sP[gbase + nf * 128 + c0 + 4] = sv[mf][nf][u * 2 + 1];
                }
            }
        PAIR_BAR(pair_bar_id);   // P rows are pair-local: only sync with sibling warp

        // ---- O += P @ V ----
        const uint32_t* sVu = smw + A_VW + s * 64 * AV;
#pragma unroll
        for (int ks = 0; ks < 8; ++ks) {
            const int kb0 = ks * 8;
            uint32_t bv[4][2];
#pragma unroll
            for (int nf = 0; nf < 4; ++nf) {
                int drow = wn * 32 + nf * 8 + lr;
                bv[nf][0] = sVu[(kb0 + lc) * AV + drow];
                bv[nf][1] = sVu[(kb0 + 4 + lc) * AV + drow];
            }
#pragma unroll
            for (int mf = 0; mf < 2; ++mf) {
                float4 av = PF[(((wm * 2 + mf) * 8 + ks) * 8 + lr) * 4 + lc];
                uint32_t ap[4] = {__float_as_uint(av.x), __float_as_uint(av.y),
                                  __float_as_uint(av.z), __float_as_uint(av.w)};
#pragma unroll
                for (int nf = 0; nf < 4; ++nf) mma8(o[mf][nf], ap, bv[nf]);
            }
        }
    }

#pragma unroll
    for (int mf = 0; mf < 2; ++mf)
#pragma unroll
        for (int u = 0; u < 2; ++u) {
            float v = l_acc[mf][u];
            v += __shfl_xor_sync(0xffffffffu, v, 1);
            v += __shfl_xor_sync(0xffffffffu, v, 2);
            l_acc[mf][u] = v;
        }
    if (lc == 0) {
#pragma unroll
        for (int mf = 0; mf < 2; ++mf)
#pragma unroll
            for (int u = 0; u < 2; ++u)
                sL[wn * 128 + wm * 32 + mf * 16 + lr + u * 8] = l_acc[mf][u];
    }
    __syncthreads();

    uint16_t* Oh = oh + ((size_t)(b * 1024 + q0)) * 512 + h * 64;
    uint16_t* Ol = ol + ((size_t)(b * 1024 + q0)) * 512 + h * 64;
#pragma unroll
    for (int mf = 0; mf < 2; ++mf)
#pragma unroll
        for (int u = 0; u < 2; ++u) {
            int row = wm * 32 + mf * 16 + lr + u * 8;
            float linv = 1.f / (sL[row] + sL[128 + row]);
#pragma unroll
            for (int nf = 0; nf < 4; ++nf) {
                int col = wn * 32 + nf * 8 + 2 * lc;
                float v0 = o[mf][nf][u * 2] * linv;
                float v1 = o[mf][nf][u * 2 + 1] * linv;
                float h0 = bf16_rn(v0), h1 = bf16_rn(v1);
                *(uint32_t*)(Oh + (size_t)row * 512 + col) = pkh(h0, h1);
                *(uint32_t*)(Ol + (size_t)row * 512 + col) = bf2(v0 - h0, v1 - h1);
            }
        }
}

// ================= launcher =================
extern "C" void kernel_launch(void* const* d_in, const int* in_sizes, int n_in,
                              void* d_out, int out_size) {
    const float* x        = (const float*)d_in[0];
    const float* context  = (const float*)d_in[1];
    const float* context2 = (const float*)d_in[2];
    const float* context3 = (const float*)d_in[3];
    const void*  mask1 = d_in[4];
    const void*  mask2 = d_in[5];
    const void*  mask3 = d_in[6];
    const float* bq  = (const float*)d_in[8];
    const float* bk1 = (const float*)d_in[10];
    const float* bv1 = (const float*)d_in[12];
    const float* bk2 = (const float*)d_in[14];
    const float* bv2 = (const float*)d_in[16];
    const float* bk3 = (const float*)d_in[18];
    const float* bv3 = (const float*)d_in[20];
    const float* Wo  = (const float*)d_in[21];
    const float* bo  = (const float*)d_in[22];
    float* out = (float*)d_out;

    uint16_t *hp, *lp, *qbp, *kbp;
    float *vp;
    cudaGetSymbolAddress((void**)&hp,  g_h);
    cudaGetSymbolAddress((void**)&lp,  g_l);
    cudaGetSymbolAddress((void**)&qbp, g_qb);
    cudaGetSymbolAddress((void**)&kbp, g_kb);
    cudaGetSymbolAddress((void**)&vp,  g_v);

    const int smem_gemm = 2 * G_STW * 4;
    const int smem_attn = A_TOTW * 4;
    static bool once = false;
    static cudaStream_t s2;
    static cudaEvent_t ev1, ev2;
    if (!once) {
        cudaFuncSetAttribute(gemm_jobs, cudaFuncAttributeMaxDynamicSharedMemorySize, smem_gemm);
        cudaFuncSetAttribute(attn_mma, cudaFuncAttributeMaxDynamicSharedMemorySize, smem_attn);
        cudaStreamCreateWithFlags(&s2, cudaStreamNonBlocking);
        cudaEventCreateWithFlags(&ev1, cudaEventDisableTiming);
        cudaEventCreateWithFlags(&ev2, cudaEventDisableTiming);
        once = true;
    }

    cudaEventRecord(ev1, 0);
    cudaStreamWaitEvent(s2, ev1, 0);
    detect_mask_kernel<<<1, 256, 0, s2>>>((const unsigned char*)mask1);
    pack_mask_kernel<<<2048, 256, 0, s2>>>(mask1, mask2, mask3);
    cudaEventRecord(ev2, s2);

    {
        SplitJobs js;
        const float* srcs[12] = {x, context, context2, context3,
                                 (const float*)d_in[7], (const float*)d_in[9],
                                 (const float*)d_in[11], (const float*)d_in[13],
                                 (const float*)d_in[15], (const float*)d_in[17],
                                 (const float*)d_in[19], Wo};
        int offs[12] = {OFF_X, OFF_C1, OFF_C2, OFF_C3,
                        OFF_WQ, OFF_WK1, OFF_WV1, OFF_WK2, OFF_WV2,
                        OFF_WK3, OFF_WV3, OFF_WO};
        int cnts[12] = {512, 512, 768, 512, 64, 64, 64, 96, 96, 32, 32, 64};
        int cum = 0;
        for (int i = 0; i < 12; ++i) {
            js.src[i] = srcs[i]; js.off[i] = offs[i];
            js.nblk[i] = cum; cum += cnts[i];
        }
        js.nblk[12] = cum;
        split_kernel<<<cum, 256>>>(js, 12);
    }

    {
        GJobs J;
        int aoffs[7]  = {OFF_X, OFF_C1, OFF_C2, OFF_C3, OFF_C1, OFF_C2, OFF_C3};
        int woffs[7]  = {OFF_WQ, OFF_WK1, OFF_WK2, OFF_WK3, OFF_WV1, OFF_WV2, OFF_WV3};
        const float* biases[7] = {bq, bk1, bk2, bk3, bv1, bv2, bv3};
        void* Cs[7]   = {qbp, kbp, kbp, kbp, vp, vp, vp};
        int Ks[7]     = {512, 512, 768, 256, 512, 768, 256};
        int Mbs[7]    = {1024, 1024, 1024, 2048, 1024, 1024, 2048};
        int ros[7]    = {0, 0, 1024, 2048, 0, 1024, 2048};
        int bss[7]    = {1024, 4096, 4096, 4096, 4096, 4096, 4096};
        int modes[7]  = {4, 2, 2, 2, 1, 1, 1};
        int blks[7]   = {256, 256, 256, 512, 256, 256, 512};
        int cum = 0;
        for (int i = 0; i < 7; ++i) {
            J.Ah[i] = hp + aoffs[i]; J.Al[i] = lp + aoffs[i];
            J.Wh[i] = hp + woffs[i]; J.Wl[i] = lp + woffs[i];
            J.bias[i] = biases[i]; J.C[i] = Cs[i];
            J.K[i] = Ks[i]; J.Mb[i] = Mbs[i]; J.rowOff[i] = ros[i];
            J.bStride[i] = bss[i]; J.mode[i] = modes[i];
            J.blk0[i] = cum; cum += blks[i];
        }
        J.blk0[7] = cum; J.njobs = 7;
        gemm_jobs<<<cum, 256, smem_gemm>>>(J);
    }

    cudaStreamWaitEvent(0, ev2, 0);

    attn_mma<<<dim3(8, 8, 4), 256, smem_attn>>>(qbp, kbp, vp, hp + OFF_AO, lp + OFF_AO);

    {
        GJobs J;
        J.Ah[0] = hp + OFF_AO; J.Al[0] = lp + OFF_AO;
        J.Wh[0] = hp + OFF_WO; J.Wl[0] = lp + OFF_WO;
        J.bias[0] = bo; J.C[0] = out;
        J.K[0] = 512; J.Mb[0] = 1024; J.rowOff[0] = 0;
        J.bStride[0] = 1024; J.mode[0] = 0;
        J.blk0[0] = 0; J.blk0[1] = 256; J.njobs = 1;
        gemm_jobs<<<256, 256, smem_gemm>>>(J);
    }
}

// round 15
// speedup vs baseline: 1.0165x; 1.0007x over previous
#include <cuda_runtime.h>
#include <cstdint>

#define EXP2C 0.1803368801111204f   /* (1/8) * log2(e) */

// ================= pools / scratch =================
#define OFF_X   0
#define OFF_C1  2097152
#define OFF_C2  4194304
#define OFF_C3  7340032
#define OFF_AO  9437184
#define OFF_WQ  11534336
#define OFF_WK1 11796480
#define OFF_WV1 12058624
#define OFF_WK2 12320768
#define OFF_WV2 12713984
#define OFF_WK3 13107200
#define OFF_WV3 13238272
#define OFF_WO  13369344
#define POOL_N  13631488

__device__ uint16_t g_h[POOL_N];
__device__ uint16_t g_l[POOL_N];
__device__ uint16_t g_qb[4 * 1024 * 512];
__device__ uint16_t g_kb[4 * 4096 * 512];
__device__ float    g_v[4 * 4096 * 512];
__device__ uint32_t g_mbits[4 * 1024 * 128];
__device__ int      g_mask_is_byte;

// ================= helpers =================
__device__ __forceinline__ uint32_t smem_u32(const void* p) {
    uint32_t a;
    asm("{ .reg .u64 t; cvta.to.shared.u64 t, %1; cvt.u32.u64 %0, t; }" : "=r"(a) : "l"(p));
    return a;
}
#define CP16(dst, src) \
    asm volatile("cp.async.cg.shared.global [%0], [%1], 16;" :: "r"(dst), "l"(src))
#define CP8(dst, src) \
    asm volatile("cp.async.ca.shared.global [%0], [%1], 8;" :: "r"(dst), "l"(src))
#define CP_COMMIT() asm volatile("cp.async.commit_group;" ::: "memory")
#define CP_WAIT(n)  asm volatile("cp.async.wait_group %0;" :: "n"(n) : "memory")
#define PAIR_BAR(id) \
    asm volatile("bar.sync %0, 64;" :: "r"(id) : "memory")

__device__ __forceinline__ float tf32_rn(float x) {
    return __uint_as_float((__float_as_uint(x) + 0x1000u) & 0xFFFFE000u);
}
__device__ __forceinline__ float bf16_rn(float x) {
    uint32_t u = __float_as_uint(x);
    u += 0x7FFFu + ((u >> 16) & 1u);
    return __uint_as_float(u & 0xFFFF0000u);
}
__device__ __forceinline__ uint32_t pkh(float a, float b) {
    return (__float_as_uint(b) & 0xFFFF0000u) | (__float_as_uint(a) >> 16);
}
__device__ __forceinline__ uint32_t bf2(float a, float b) {
    uint32_t r;
    asm("cvt.rn.bf16x2.f32 %0, %1, %2;" : "=r"(r) : "f"(b), "f"(a));
    return r;
}
__device__ __forceinline__ float ex2f(float y) {
    float r;
    asm("ex2.approx.f32 %0, %1;" : "=f"(r) : "f"(y));
    return r;
}
__device__ __forceinline__ void mma8(float* c, const uint32_t* a, const uint32_t* b) {
    asm volatile("mma.sync.aligned.m16n8k8.row.col.f32.tf32.tf32.f32 "
        "{%0,%1,%2,%3},{%4,%5,%6,%7},{%8,%9},{%0,%1,%2,%3};"
        : "+f"(c[0]), "+f"(c[1]), "+f"(c[2]), "+f"(c[3])
        : "r"(a[0]), "r"(a[1]), "r"(a[2]), "r"(a[3]), "r"(b[0]), "r"(b[1]));
}
__device__ __forceinline__ void mma16(float* c, const uint32_t* a, const uint32_t* b) {
    asm volatile("mma.sync.aligned.m16n8k16.row.col.f32.bf16.bf16.f32 "
        "{%0,%1,%2,%3},{%4,%5,%6,%7},{%8,%9},{%0,%1,%2,%3};"
        : "+f"(c[0]), "+f"(c[1]), "+f"(c[2]), "+f"(c[3])
        : "r"(a[0]), "r"(a[1]), "r"(a[2]), "r"(a[3]), "r"(b[0]), "r"(b[1]));
}
__device__ __forceinline__ void ldsm_x4(uint32_t* r, uint32_t addr) {
    asm volatile("ldmatrix.sync.aligned.m8n8.x4.shared.b16 {%0,%1,%2,%3}, [%4];"
        : "=r"(r[0]), "=r"(r[1]), "=r"(r[2]), "=r"(r[3]) : "r"(addr));
}
__device__ __forceinline__ void ldsm_x4_t(uint32_t* r, uint32_t addr) {
    asm volatile("ldmatrix.sync.aligned.m8n8.x4.trans.shared.b16 {%0,%1,%2,%3}, [%4];"
        : "=r"(r[0]), "=r"(r[1]), "=r"(r[2]), "=r"(r[3]) : "r"(addr));
}

// ================= mask detect + bit-pack =================
__global__ void detect_mask_kernel(const unsigned char* __restrict__ m) {
    __shared__ int any;
    if (threadIdx.x == 0) any = 0;
    __syncthreads();
    int found = 0;
    for (int i = threadIdx.x; i < 4096; i += blockDim.x)
        if ((i & 3) == 1 && m[i]) found = 1;
    if (found) atomicOr(&any, 1);
    __syncthreads();
    if (threadIdx.x == 0) g_mask_is_byte = any;
}

__global__ void pack_mask_kernel(const void* __restrict__ m1, const void* __restrict__ m2,
                                 const void* __restrict__ m3) {
    int idx = blockIdx.x * blockDim.x + threadIdx.x;
    if (idx >= 4 * 1024 * 128) return;
    int w = idx & 127, q = (idx >> 7) & 1023, b = idx >> 17;
    int k0 = w * 32;
    const void* mp; int nseg, jl;
    if (k0 < 1024)      { mp = m1; nseg = 1024; jl = k0; }
    else if (k0 < 2048) { mp = m2; nseg = 1024; jl = k0 - 1024; }
    else                { mp = m3; nseg = 2048; jl = k0 - 2048; }
    size_t base = (size_t)(b * 1024 + q) * nseg + jl;
    uint32_t bits = 0;
    if (g_mask_is_byte) {
        const uint4* p = (const uint4*)((const unsigned char*)mp + base);
        uint4 a = p[0], c = p[1];
        uint32_t ws[8] = {a.x, a.y, a.z, a.w, c.x, c.y, c.z, c.w};
#pragma unroll
        for (int wi = 0; wi < 8; ++wi)
#pragma unroll
            for (int by = 0; by < 4; ++by)
                if ((ws[wi] >> (8 * by)) & 0xFFu) bits |= 1u << (wi * 4 + by);
    } else {
        const uint4* p = (const uint4*)((const uint32_t*)mp + base);
#pragma unroll
        for (int wi = 0; wi < 8; ++wi) {
            uint4 v = p[wi];
            if (v.x) bits |= 1u << (wi * 4 + 0);
            if (v.y) bits |= 1u << (wi * 4 + 1);
            if (v.z) bits |= 1u << (wi * 4 + 2);
            if (v.w) bits |= 1u << (wi * 4 + 3);
        }
    }
    g_mbits[idx] = bits;
}

// ================= bf16 hi/lo split (pre-pass) =================
struct SplitJobs {
    const float* src[12];
    int nblk[13];
    int off[12];
};
__global__ __launch_bounds__(256) void split_kernel(SplitJobs j, int njobs) {
    int bid = blockIdx.x;
    int ji = 0;
    while (ji + 1 < njobs && bid >= j.nblk[ji + 1]) ++ji;
    int local = bid - j.nblk[ji];
    const float4* src = (const float4*)j.src[ji];
    uint2* dh = (uint2*)(g_h + j.off[ji]);
    uint2* dl = (uint2*)(g_l + j.off[ji]);
    size_t base4 = (size_t)local * 1024;
#pragma unroll
    for (int it = 0; it < 4; ++it) {
        size_t i4 = base4 + it * 256 + threadIdx.x;
        float4 v = src[i4];
        float h0 = bf16_rn(v.x), h1 = bf16_rn(v.y), h2 = bf16_rn(v.z), h3 = bf16_rn(v.w);
        dh[i4] = make_uint2(pkh(h0, h1), pkh(h2, h3));
        dl[i4] = make_uint2(bf2(v.x - h0, v.y - h1), bf2(v.z - h2, v.w - h3));
    }
}

// ================= 3xBF16 HMMA GEMM, register-pipelined steps =================
#define G_OAL 4608
#define G_OBH 9216
#define G_OBL 11520
#define G_STW 13824
struct GJobs {
    const uint16_t* Ah[7]; const uint16_t* Al[7];
    const uint16_t* Wh[7]; const uint16_t* Wl[7];
    const float* bias[7];  void* C[7];
    int K[7], Mb[7], rowOff[7], bStride[7], mode[7];
    int blk0[8];
    int njobs;
};
// mode: 0 = fp32 out, 1 = tf32-rounded fp32 out, 2 = bf16 out, 4 = bf16 out scaled by EXP2C
__global__ __launch_bounds__(256, 2) void gemm_jobs(GJobs J) {
    extern __shared__ uint32_t smw[];
    int j = 0;
    while (j + 1 < J.njobs && (int)blockIdx.x >= J.blk0[j + 1]) ++j;
    const int lb = blockIdx.x - J.blk0[j];
    const uint16_t* __restrict__ Ah = J.Ah[j];
    const uint16_t* __restrict__ Al = J.Al[j];
    const uint16_t* __restrict__ Wh = J.Wh[j];
    const uint16_t* __restrict__ Wl = J.Wl[j];
    const float* __restrict__ bias = J.bias[j];
    void* Cv = J.C[j];
    const int K = J.K[j], Mb = J.Mb[j], rowOff = J.rowOff[j];
    const int bStride = J.bStride[j], mode = J.mode[j];

    const int tid = threadIdx.x, lane = tid & 31, wid = tid >> 5;
    const int wm = wid & 3, wn = wid >> 2;
    const int lr = lane >> 2, lc = lane & 3;
    const int m0 = (lb >> 3) * 128, n0 = (lb & 7) * 64;
    const int l16 = lane & 15, lh8 = (lane >> 4) << 3;

    float acc[2][4][4];
#pragma unroll
    for (int i = 0; i < 2; ++i)
#pragma unroll
        for (int jj = 0; jj < 4; ++jj)
#pragma unroll
            for (int e = 0; e < 4; ++e) acc[i][jj][e] = 0.f;

    const int nK = K >> 6;
    const uint32_t ub = smem_u32(smw);

#define STAGE(c, s) do { \
    const uint32_t d0 = ub + (s) * G_STW * 4; \
    _Pragma("unroll") \
    for (int it = 0; it < 4; ++it) { \
        int id = it * 256 + tid, row = id >> 3, seg = id & 7; \
        size_t so = (size_t)(m0 + row) * K + (c) * 64 + seg * 8; \
        uint32_t dw = (row * 36 + seg * 4) * 4; \
        CP16(d0 + dw, Ah + so); \
        CP16(d0 + G_OAL * 4 + dw, Al + so); \
    } \
    _Pragma("unroll") \
    for (int it = 0; it < 2; ++it) { \
        int id = it * 256 + tid, row = id >> 3, seg = id & 7; \
        size_t so = (size_t)((c) * 64 + row) * 512 + n0 + seg * 8; \
        uint32_t dw = (row * 36 + seg * 4) * 4; \
        CP16(d0 + G_OBH * 4 + dw, Wh + so); \
        CP16(d0 + G_OBL * 4 + dw, Wl + so); \
    } \
    CP_COMMIT(); \
} while (0)

// fragment prefetch: fa = {ah0, ah1, al0, al1}, fb = {bh0, bh1, bl0, bl1}
#define LOADF(sb_, st_, bf_) do { \
    const int k0_ = (st_) * 16; \
    _Pragma("unroll") \
    for (int mf = 0; mf < 2; ++mf) { \
        int row = wm * 32 + mf * 16 + l16; \
        uint32_t ad = (sb_) + (row * 36 + ((k0_ + lh8) >> 1)) * 4; \
        ldsm_x4(fa[bf_][mf], ad); \
        ldsm_x4(fa[bf_][2 + mf], ad + G_OAL * 4); \
    } \
    _Pragma("unroll") \
    for (int p = 0; p < 2; ++p) { \
        int row = k0_ + l16; \
        int col = wn * 32 + p * 16 + lh8; \
        uint32_t bd = (sb_) + (G_OBH + row * 36 + (col >> 1)) * 4; \
        ldsm_x4_t(fb[bf_][p], bd); \
        ldsm_x4_t(fb[bf_][2 + p], bd + (G_OBL - G_OBH) * 4); \
    } \
} while (0)

    uint32_t fa[2][4][4], fb[2][4][4];

    STAGE(0, 0);
    for (int c = 0; c < nK; ++c) {
        const int s = c & 1;
        if (c + 1 < nK) { STAGE(c + 1, s ^ 1); CP_WAIT(1); }
        else            { CP_WAIT(0); }
        __syncthreads();
        const uint32_t sb = ub + s * G_STW * 4;
        LOADF(sb, 0, 0);
#pragma unroll
        for (int st = 0; st < 4; ++st) {
            const int bf = st & 1;
            if (st < 3) LOADF(sb, st + 1, bf ^ 1);
            // term-major mma, per-accumulator order hh -> hl -> lh preserved
#pragma unroll
            for (int mf = 0; mf < 2; ++mf)
#pragma unroll
                for (int p = 0; p < 2; ++p) {
                    mma16(acc[mf][p * 2 + 0], fa[bf][mf], &fb[bf][p][0]);
                    mma16(acc[mf][p * 2 + 1], fa[bf][mf], &fb[bf][p][2]);
                }
#pragma unroll
            for (int mf = 0; mf < 2; ++mf)
#pragma unroll
                for (int p = 0; p < 2; ++p) {
                    mma16(acc[mf][p * 2 + 0], fa[bf][mf], &fb[bf][2 + p][0]);
                    mma16(acc[mf][p * 2 + 1], fa[bf][mf], &fb[bf][2 + p][2]);
                }
#pragma unroll
            for (int mf = 0; mf < 2; ++mf)
#pragma unroll
                for (int p = 0; p < 2; ++p) {
                    mma16(acc[mf][p * 2 + 0], fa[bf][2 + mf], &fb[bf][p][0]);
                    mma16(acc[mf][p * 2 + 1], fa[bf][2 + mf], &fb[bf][p][2]);
                }
        }
        __syncthreads();
    }
#undef STAGE
#undef LOADF
#pragma unroll
    for (int mf = 0; mf < 2; ++mf) {
        int r = m0 + wm * 32 + mf * 16 + lr;
        int b0i = r / Mb;
        size_t or0 = (size_t)b0i * bStride + rowOff + (r - b0i * Mb);
        int r2 = r + 8;
        int b1i = r2 / Mb;
        size_t or1 = (size_t)b1i * bStride + rowOff + (r2 - b1i * Mb);
#pragma unroll
        for (int nf = 0; nf < 4; ++nf) {
            int col = n0 + wn * 32 + nf * 8 + 2 * lc;
            float bv0 = bias[col], bv1 = bias[col + 1];
            float v00 = acc[mf][nf][0] + bv0, v01 = acc[mf][nf][1] + bv1;
            float v10 = acc[mf][nf][2] + bv0, v11 = acc[mf][nf][3] + bv1;
            if (mode >= 2) {
                if (mode == 4) { v00 *= EXP2C; v01 *= EXP2C; v10 *= EXP2C; v11 *= EXP2C; }
                uint16_t* Cb = (uint16_t*)Cv;
                *(uint32_t*)(Cb + or0 * 512 + col) = pkh(bf16_rn(v00), bf16_rn(v01));
                *(uint32_t*)(Cb + or1 * 512 + col) = pkh(bf16_rn(v10), bf16_rn(v11));
            } else {
                float* C = (float*)Cv;
                if (mode == 1) {
                    v00 = tf32_rn(v00); v01 = tf32_rn(v01);
                    v10 = tf32_rn(v10); v11 = tf32_rn(v11);
                }
                *(float2*)(C + or0 * 512 + col) = make_float2(v00, v01);
                *(float2*)(C + or1 * 512 + col) = make_float2(v10, v11);
            }
        }
    }
}

// ================= flash attention: pair-barrier phase overlap =================
#define A_QW 0
#define A_KW 4608
#define A_VW 9216
#define A_PW 18432
#define A_MW 27136
#define A_LW 27648
#define A_TOTW 27904
#define AV 72

__global__ __launch_bounds__(256, 2) void attn_mma(
    const uint16_t* __restrict__ qb, const uint16_t* __restrict__ kb,
    const float* __restrict__ vb,
    uint16_t* __restrict__ oh, uint16_t* __restrict__ ol)
{
    extern __shared__ uint32_t smw[];
    float* smf = (float*)smw;
    uint32_t* sM = smw + A_MW;
    float* sP = smf + A_PW;      // fragment-major
    float* sL = smf + A_LW;
    const float4* PF = (const float4*)sP;

    const int tid = threadIdx.x, lane = tid & 31, wid = tid >> 5;
    const int wm = wid & 3, wn = wid >> 2;
    const int lr = lane >> 2, lc = lane & 3;
    const int ln8 = lane & 7;
    const int pair_bar_id = 1 + wm;
    const int q0 = blockIdx.x * 128, h = blockIdx.y, b = blockIdx.z;

    const uint16_t* Qg = qb + ((size_t)(b * 1024 + q0)) * 512 + h * 64;
    const uint16_t* Kg = kb + ((size_t)(b * 4096)) * 512 + h * 64;
    const float*    Vg = vb + ((size_t)(b * 4096)) * 512 + h * 64;
    const uint32_t* mbase = g_mbits + ((size_t)(b * 1024 + q0)) * 128;
    const uint32_t ubase = smem_u32(smw);
    const uint32_t uQ = ubase + A_QW * 4, uK = ubase + A_KW * 4;
    const uint32_t uV = ubase + A_VW * 4, uM = ubase + A_MW * 4;

#pragma unroll
    for (int it = 0; it < 4; ++it) {
        int id = it * 256 + tid, row = id >> 3, seg = id & 7;
        CP16(uQ + (row * 36 + seg * 4) * 4, Qg + (size_t)row * 512 + seg * 8);
    }
#pragma unroll
    for (int it = 0; it < 2; ++it) {
        int id = it * 256 + tid, row = id >> 3, seg = id & 7;
        CP16(uK + (row * 36 + seg * 4) * 4, Kg + (size_t)row * 512 + seg * 8);
    }
#pragma unroll
    for (int it = 0; it < 4; ++it) {
        int id = it * 256 + tid, row = id >> 4, seg = id & 15;
        CP16(uV + (row * AV + seg * 4) * 4, Vg + (size_t)row * 512 + seg * 4);
    }
    if (tid < 128) CP8(uM + tid * 8, (const char*)(mbase + (size_t)tid * 128));
    CP_COMMIT();
    CP_WAIT(0);
    __syncthreads();

    float o[2][4][4];
    float l_acc[2][2];
#pragma unroll
    for (int i = 0; i < 2; ++i) {
        l_acc[i][0] = 0.f; l_acc[i][1] = 0.f;
#pragma unroll
        for (int jj = 0; jj < 4; ++jj)
#pragma unroll
            for (int e = 0; e < 4; ++e) o[i][jj][e] = 0.f;
    }

    for (int t = 0; t < 64; ++t) {
        const int s = t & 1;
        if (t > 0) { CP_WAIT(0); __syncthreads(); }   // one full-CTA sync per tile

        if (t < 63) {
            const uint16_t* Kn = Kg + (size_t)(t + 1) * 64 * 512;
            const float* Vn = Vg + (size_t)(t + 1) * 64 * 512;
            const uint32_t dK = uK + (s ^ 1) * 2304 * 4;
            const uint32_t dV = uV + (s ^ 1) * 64 * AV * 4;
#pragma unroll
            for (int it = 0; it < 2; ++it) {
                int id = it * 256 + tid, row = id >> 3, seg = id & 7;
                CP16(dK + (row * 36 + seg * 4) * 4, Kn + (size_t)row * 512 + seg * 8);
            }
#pragma unroll
            for (int it = 0; it < 4; ++it) {
                int id = it * 256 + tid, row = id >> 4, seg = id & 15;
                CP16(dV + (row * AV + seg * 4) * 4, Vn + (size_t)row * 512 + seg * 4);
            }
            if (tid < 128)
                CP8(uM + (s ^ 1) * 1024 + tid * 8,
                    (const char*)(mbase + (size_t)tid * 128 + (t + 1) * 2));
            CP_COMMIT();
        }

        // ---- S' = (Q*EXP2C) K^T ----
        const uint32_t uKs = uK + s * 2304 * 4;
        float sv[2][4][4];
#pragma unroll
        for (int i = 0; i < 2; ++i)
#pragma unroll
            for (int jj = 0; jj < 4; ++jj)
#pragma unroll
                for (int e = 0; e < 4; ++e) sv[i][jj][e] = 0.f;
#pragma unroll
        for (int ks = 0; ks < 4; ++ks) {
            int kcb = ks * 16 + ((lane >> 3) & 1) * 8;
            int nrow = wn * 32 + (lane >> 4) * 8 + ln8;
            uint32_t bk0[4], bk1[4];
            ldsm_x4(bk0, uKs + (nrow * 36 + (kcb >> 1)) * 4);
            ldsm_x4(bk1, uKs + ((nrow + 16) * 36 + (kcb >> 1)) * 4);
#pragma unroll
            for (int mf = 0; mf < 2; ++mf) {
                int qrow = wm * 32 + mf * 16 + ((lane >> 3) & 1) * 8 + ln8;
                int kc = ks * 16 + (lane >> 4) * 8;
                uint32_t aq[4];
                ldsm_x4(aq, uQ + (qrow * 36 + (kc >> 1)) * 4);
                mma16(sv[mf][0], aq, &bk0[0]);
                mma16(sv[mf][1], aq, &bk0[2]);
                mma16(sv[mf][2], aq, &bk1[0]);
                mma16(sv[mf][3], aq, &bk1[2]);
            }
        }

        // ---- masked no-max softmax + fragment-major P write ----
        // P left in fp32; mma8 truncates to tf32 in HW (bias ~6e-5, negligible)
#pragma unroll
        for (int mf = 0; mf < 2; ++mf)
#pragma unroll
            for (int u = 0; u < 2; ++u) {
                int row = wm * 32 + mf * 16 + lr + u * 8;
                uint32_t mw = sM[s * 256 + row * 2 + wn];
                float rs = 0.f;
#pragma unroll
                for (int nf = 0; nf < 4; ++nf) {
#pragma unroll
                    for (int q2 = 0; q2 < 2; ++q2) {
                        int cr = u * 2 + q2;
                        int cl = nf * 8 + 2 * lc + q2;
                        float p = ex2f(sv[mf][nf][cr]);
                        p = ((mw >> cl) & 1u) ? p : 0.f;
                        rs += p;
                        sv[mf][nf][cr] = p;
                    }
                }
                l_acc[mf][u] += rs;
                int gbase = (((wm * 2 + mf) * 8 + wn * 4) * 8 + lr) * 16 + u + 2 * (lc >> 1);
                int c0 = (lc & 1) * 8;
#pragma unroll
                for (int nf = 0; nf < 4; ++nf) {
                    sP[gbase + nf * 128 + c0]     = sv[mf][nf][u * 2];
                    sP[gbase + nf * 128 + c0 + 4] = sv[mf][nf][u * 2 + 1];
                }
            }
        PAIR_BAR(pair_bar_id);

        // ---- O += P @ V ----
        const uint32_t* sVu = smw + A_VW + s * 64 * AV;
#pragma unroll
        for (int ks = 0; ks < 8; ++ks) {
            const int kb0 = ks * 8;
            uint32_t bv[4][2];
#pragma unroll
            for (int nf = 0; nf < 4; ++nf) {
                int drow = wn * 32 + nf * 8 + lr;
                bv[nf][0] = sVu[(kb0 + lc) * AV + drow];
                bv[nf][1] = sVu[(kb0 + 4 + lc) * AV + drow];
            }
#pragma unroll
            for (int mf = 0; mf < 2; ++mf) {
                float4 av = PF[(((wm * 2 + mf) * 8 + ks) * 8 + lr) * 4 + lc];
                uint32_t ap[4] = {__float_as_uint(av.x), __float_as_uint(av.y),
                                  __float_as_uint(av.z), __float_as_uint(av.w)};
#pragma unroll
                for (int nf = 0; nf < 4; ++nf) mma8(o[mf][nf], ap, bv[nf]);
            }
        }
    }

#pragma unroll
    for (int mf = 0; mf < 2; ++mf)
#pragma unroll
        for (int u = 0; u < 2; ++u) {
            float v = l_acc[mf][u];
            v += __shfl_xor_sync(0xffffffffu, v, 1);
            v += __shfl_xor_sync(0xffffffffu, v, 2);
            l_acc[mf][u] = v;
        }
    if (lc == 0) {
#pragma unroll
        for (int mf = 0; mf < 2; ++mf)
#pragma unroll
            for (int u = 0; u < 2; ++u)
                sL[wn * 128 + wm * 32 + mf * 16 + lr + u * 8] = l_acc[mf][u];
    }
    __syncthreads();

    uint16_t* Oh = oh + ((size_t)(b * 1024 + q0)) * 512 + h * 64;
    uint16_t* Ol = ol + ((size_t)(b * 1024 + q0)) * 512 + h * 64;
#pragma unroll
    for (int mf = 0; mf < 2; ++mf)
#pragma unroll
        for (int u = 0; u < 2; ++u) {
            int row = wm * 32 + mf * 16 + lr + u * 8;
            float linv = 1.f / (sL[row] + sL[128 + row]);
#pragma unroll
            for (int nf = 0; nf < 4; ++nf) {
                int col = wn * 32 + nf * 8 + 2 * lc;
                float v0 = o[mf][nf][u * 2] * linv;
                float v1 = o[mf][nf][u * 2 + 1] * linv;
                float h0 = bf16_rn(v0), h1 = bf16_rn(v1);
                *(uint32_t*)(Oh + (size_t)row * 512 + col) = pkh(h0, h1);
                *(uint32_t*)(Ol + (size_t)row * 512 + col) = bf2(v0 - h0, v1 - h1);
            }
        }
}

// ================= launcher =================
extern "C" void kernel_launch(void* const* d_in, const int* in_sizes, int n_in,
                              void* d_out, int out_size) {
    const float* x        = (const float*)d_in[0];
    const float* context  = (const float*)d_in[1];
    const float* context2 = (const float*)d_in[2];
    const float* context3 = (const float*)d_in[3];
    const void*  mask1 = d_in[4];
    const void*  mask2 = d_in[5];
    const void*  mask3 = d_in[6];
    const float* bq  = (const float*)d_in[8];
    const float* bk1 = (const float*)d_in[10];
    const float* bv1 = (const float*)d_in[12];
    const float* bk2 = (const float*)d_in[14];
    const float* bv2 = (const float*)d_in[16];
    const float* bk3 = (const float*)d_in[18];
    const float* bv3 = (const float*)d_in[20];
    const float* Wo  = (const float*)d_in[21];
    const float* bo  = (const float*)d_in[22];
    float* out = (float*)d_out;

    uint16_t *hp, *lp, *qbp, *kbp;
    float *vp;
    cudaGetSymbolAddress((void**)&hp,  g_h);
    cudaGetSymbolAddress((void**)&lp,  g_l);
    cudaGetSymbolAddress((void**)&qbp, g_qb);
    cudaGetSymbolAddress((void**)&kbp, g_kb);
    cudaGetSymbolAddress((void**)&vp,  g_v);

    const int smem_gemm = 2 * G_STW * 4;
    const int smem_attn = A_TOTW * 4;
    static bool once = false;
    static cudaStream_t s2;
    static cudaEvent_t ev1, ev2;
    if (!once) {
        cudaFuncSetAttribute(gemm_jobs, cudaFuncAttributeMaxDynamicSharedMemorySize, smem_gemm);
        cudaFuncSetAttribute(attn_mma, cudaFuncAttributeMaxDynamicSharedMemorySize, smem_attn);
        cudaStreamCreateWithFlags(&s2, cudaStreamNonBlocking);
        cudaEventCreateWithFlags(&ev1, cudaEventDisableTiming);
        cudaEventCreateWithFlags(&ev2, cudaEventDisableTiming);
        once = true;
    }

    cudaEventRecord(ev1, 0);
    cudaStreamWaitEvent(s2, ev1, 0);
    detect_mask_kernel<<<1, 256, 0, s2>>>((const unsigned char*)mask1);
    pack_mask_kernel<<<2048, 256, 0, s2>>>(mask1, mask2, mask3);
    cudaEventRecord(ev2, s2);

    {
        SplitJobs js;
        const float* srcs[12] = {x, context, context2, context3,
                                 (const float*)d_in[7], (const float*)d_in[9],
                                 (const float*)d_in[11], (const float*)d_in[13],
                                 (const float*)d_in[15], (const float*)d_in[17],
                                 (const float*)d_in[19], Wo};
        int offs[12] = {OFF_X, OFF_C1, OFF_C2, OFF_C3,
                        OFF_WQ, OFF_WK1, OFF_WV1, OFF_WK2, OFF_WV2,
                        OFF_WK3, OFF_WV3, OFF_WO};
        int cnts[12] = {512, 512, 768, 512, 64, 64, 64, 96, 96, 32, 32, 64};
        int cum = 0;
        for (int i = 0; i < 12; ++i) {
            js.src[i] = srcs[i]; js.off[i] = offs[i];
            js.nblk[i] = cum; cum += cnts[i];
        }
        js.nblk[12] = cum;
        split_kernel<<<cum, 256>>>(js, 12);
    }

    {
        GJobs J;
        int aoffs[7]  = {OFF_X, OFF_C1, OFF_C2, OFF_C3, OFF_C1, OFF_C2, OFF_C3};
        int woffs[7]  = {OFF_WQ, OFF_WK1, OFF_WK2, OFF_WK3, OFF_WV1, OFF_WV2, OFF_WV3};
        const float* biases[7] = {bq, bk1, bk2, bk3, bv1, bv2, bv3};
        void* Cs[7]   = {qbp, kbp, kbp, kbp, vp, vp, vp};
        int Ks[7]     = {512, 512, 768, 256, 512, 768, 256};
        int Mbs[7]    = {1024, 1024, 1024, 2048, 1024, 1024, 2048};
        int ros[7]    = {0, 0, 1024, 2048, 0, 1024, 2048};
        int bss[7]    = {1024, 4096, 4096, 4096, 4096, 4096, 4096};
        int modes[7]  = {4, 2, 2, 2, 1, 1, 1};
        int blks[7]   = {256, 256, 256, 512, 256, 256, 512};
        int cum = 0;
        for (int i = 0; i < 7; ++i) {
            J.Ah[i] = hp + aoffs[i]; J.Al[i] = lp + aoffs[i];
            J.Wh[i] = hp + woffs[i]; J.Wl[i] = lp + woffs[i];
            J.bias[i] = biases[i]; J.C[i] = Cs[i];
            J.K[i] = Ks[i]; J.Mb[i] = Mbs[i]; J.rowOff[i] = ros[i];
            J.bStride[i] = bss[i]; J.mode[i] = modes[i];
            J.blk0[i] = cum; cum += blks[i];
        }
        J.blk0[7] = cum; J.njobs = 7;
        gemm_jobs<<<cum, 256, smem_gemm>>>(J);
    }

    cudaStreamWaitEvent(0, ev2, 0);

    attn_mma<<<dim3(8, 8, 4), 256, smem_attn>>>(qbp, kbp, vp, hp + OFF_AO, lp + OFF_AO);

    {
        GJobs J;
        J.Ah[0] = hp + OFF_AO; J.Al[0] = lp + OFF_AO;
        J.Wh[0] = hp + OFF_WO; J.Wl[0] = lp + OFF_WO;
        J.bias[0] = bo; J.C[0] = out;
        J.K[0] = 512; J.Mb[0] = 1024; J.rowOff[0] = 0;
        J.bStride[0] = 1024; J.mode[0] = 0;
        J.blk0[0] = 0; J.blk0[1] = 256; J.njobs = 1;
        gemm_jobs<<<256, 256, smem_gemm>>>(J);
    }
}

// round 16
// speedup vs baseline: 1.0377x; 1.0209x over previous
#include <cuda_runtime.h>
#include <cstdint>

#define EXP2C 0.1803368801111204f   /* (1/8) * log2(e) */

// ================= pools / scratch =================
#define OFF_X   0
#define OFF_C1  2097152
#define OFF_C2  4194304
#define OFF_C3  7340032
#define OFF_AO  9437184
#define OFF_WQ  11534336
#define OFF_WK1 11796480
#define OFF_WV1 12058624
#define OFF_WK2 12320768
#define OFF_WV2 12713984
#define OFF_WK3 13107200
#define OFF_WV3 13238272
#define OFF_WO  13369344
#define POOL_N  13631488

__device__ uint16_t g_h[POOL_N];
__device__ uint16_t g_l[POOL_N];
__device__ uint16_t g_qb[4 * 1024 * 512];
__device__ uint16_t g_kb[4 * 4096 * 512];
__device__ float    g_v[4 * 4096 * 512];
__device__ uint32_t g_mbits[4 * 1024 * 128];
__device__ int      g_mask_is_byte;

// ================= helpers =================
__device__ __forceinline__ uint32_t smem_u32(const void* p) {
    uint32_t a;
    asm("{ .reg .u64 t; cvta.to.shared.u64 t, %1; cvt.u32.u64 %0, t; }" : "=r"(a) : "l"(p));
    return a;
}
#define CP16(dst, src) \
    asm volatile("cp.async.cg.shared.global [%0], [%1], 16;" :: "r"(dst), "l"(src))
#define CP8(dst, src) \
    asm volatile("cp.async.ca.shared.global [%0], [%1], 8;" :: "r"(dst), "l"(src))
#define CP_COMMIT() asm volatile("cp.async.commit_group;" ::: "memory")
#define CP_WAIT(n)  asm volatile("cp.async.wait_group %0;" :: "n"(n) : "memory")
#define PAIR_BAR(id) \
    asm volatile("bar.sync %0, 64;" :: "r"(id) : "memory")

__device__ __forceinline__ float tf32_rn(float x) {
    return __uint_as_float((__float_as_uint(x) + 0x1000u) & 0xFFFFE000u);
}
__device__ __forceinline__ float bf16_rn(float x) {
    uint32_t u = __float_as_uint(x);
    u += 0x7FFFu + ((u >> 16) & 1u);
    return __uint_as_float(u & 0xFFFF0000u);
}
__device__ __forceinline__ uint32_t pkh(float a, float b) {
    return (__float_as_uint(b) & 0xFFFF0000u) | (__float_as_uint(a) >> 16);
}
__device__ __forceinline__ uint32_t bf2(float a, float b) {
    uint32_t r;
    asm("cvt.rn.bf16x2.f32 %0, %1, %2;" : "=r"(r) : "f"(b), "f"(a));
    return r;
}
__device__ __forceinline__ float ex2f(float y) {
    float r;
    asm("ex2.approx.f32 %0, %1;" : "=f"(r) : "f"(y));
    return r;
}
__device__ __forceinline__ void mma8(float* c, const uint32_t* a, const uint32_t* b) {
    asm volatile("mma.sync.aligned.m16n8k8.row.col.f32.tf32.tf32.f32 "
        "{%0,%1,%2,%3},{%4,%5,%6,%7},{%8,%9},{%0,%1,%2,%3};"
        : "+f"(c[0]), "+f"(c[1]), "+f"(c[2]), "+f"(c[3])
        : "r"(a[0]), "r"(a[1]), "r"(a[2]), "r"(a[3]), "r"(b[0]), "r"(b[1]));
}
__device__ __forceinline__ void mma16(float* c, const uint32_t* a, const uint32_t* b) {
    asm volatile("mma.sync.aligned.m16n8k16.row.col.f32.bf16.bf16.f32 "
        "{%0,%1,%2,%3},{%4,%5,%6,%7},{%8,%9},{%0,%1,%2,%3};"
        : "+f"(c[0]), "+f"(c[1]), "+f"(c[2]), "+f"(c[3])
        : "r"(a[0]), "r"(a[1]), "r"(a[2]), "r"(a[3]), "r"(b[0]), "r"(b[1]));
}
__device__ __forceinline__ void ldsm_x4(uint32_t* r, uint32_t addr) {
    asm volatile("ldmatrix.sync.aligned.m8n8.x4.shared.b16 {%0,%1,%2,%3}, [%4];"
        : "=r"(r[0]), "=r"(r[1]), "=r"(r[2]), "=r"(r[3]) : "r"(addr));
}
__device__ __forceinline__ void ldsm_x4_t(uint32_t* r, uint32_t addr) {
    asm volatile("ldmatrix.sync.aligned.m8n8.x4.trans.shared.b16 {%0,%1,%2,%3}, [%4];"
        : "=r"(r[0]), "=r"(r[1]), "=r"(r[2]), "=r"(r[3]) : "r"(addr));
}

// ================= mask detect + bit-pack =================
__global__ void detect_mask_kernel(const unsigned char* __restrict__ m) {
    __shared__ int any;
    if (threadIdx.x == 0) any = 0;
    __syncthreads();
    int found = 0;
    for (int i = threadIdx.x; i < 4096; i += blockDim.x)
        if ((i & 3) == 1 && m[i]) found = 1;
    if (found) atomicOr(&any, 1);
    __syncthreads();
    if (threadIdx.x == 0) g_mask_is_byte = any;
}

__global__ void pack_mask_kernel(const void* __restrict__ m1, const void* __restrict__ m2,
                                 const void* __restrict__ m3) {
    int idx = blockIdx.x * blockDim.x + threadIdx.x;
    if (idx >= 4 * 1024 * 128) return;
    int w = idx & 127, q = (idx >> 7) & 1023, b = idx >> 17;
    int k0 = w * 32;
    const void* mp; int nseg, jl;
    if (k0 < 1024)      { mp = m1; nseg = 1024; jl = k0; }
    else if (k0 < 2048) { mp = m2; nseg = 1024; jl = k0 - 1024; }
    else                { mp = m3; nseg = 2048; jl = k0 - 2048; }
    size_t base = (size_t)(b * 1024 + q) * nseg + jl;
    uint32_t bits = 0;
    if (g_mask_is_byte) {
        const uint4* p = (const uint4*)((const unsigned char*)mp + base);
        uint4 a = p[0], c = p[1];
        uint32_t ws[8] = {a.x, a.y, a.z, a.w, c.x, c.y, c.z, c.w};
#pragma unroll
        for (int wi = 0; wi < 8; ++wi)
#pragma unroll
            for (int by = 0; by < 4; ++by)
                if ((ws[wi] >> (8 * by)) & 0xFFu) bits |= 1u << (wi * 4 + by);
    } else {
        const uint4* p = (const uint4*)((const uint32_t*)mp + base);
#pragma unroll
        for (int wi = 0; wi < 8; ++wi) {
            uint4 v = p[wi];
            if (v.x) bits |= 1u << (wi * 4 + 0);
            if (v.y) bits |= 1u << (wi * 4 + 1);
            if (v.z) bits |= 1u << (wi * 4 + 2);
            if (v.w) bits |= 1u << (wi * 4 + 3);
        }
    }
    g_mbits[idx] = bits;
}

// ================= bf16 hi/lo split (pre-pass) =================
struct SplitJobs {
    const float* src[12];
    int nblk[13];
    int off[12];
};
__global__ __launch_bounds__(256) void split_kernel(SplitJobs j, int njobs) {
    int bid = blockIdx.x;
    int ji = 0;
    while (ji + 1 < njobs && bid >= j.nblk[ji + 1]) ++ji;
    int local = bid - j.nblk[ji];
    const float4* src = (const float4*)j.src[ji];
    uint2* dh = (uint2*)(g_h + j.off[ji]);
    uint2* dl = (uint2*)(g_l + j.off[ji]);
    size_t base4 = (size_t)local * 1024;
#pragma unroll
    for (int it = 0; it < 4; ++it) {
        size_t i4 = base4 + it * 256 + threadIdx.x;
        float4 v = src[i4];
        float h0 = bf16_rn(v.x), h1 = bf16_rn(v.y), h2 = bf16_rn(v.z), h3 = bf16_rn(v.w);
        dh[i4] = make_uint2(pkh(h0, h1), pkh(h2, h3));
        dl[i4] = make_uint2(bf2(v.x - h0, v.y - h1), bf2(v.z - h2, v.w - h3));
    }
}

// ================= 3xBF16 HMMA GEMM (R14 inner loop — empirical best) =================
#define G_OAL 4608
#define G_OBH 9216
#define G_OBL 11520
#define G_STW 13824
struct GJobs {
    const uint16_t* Ah[7]; const uint16_t* Al[7];
    const uint16_t* Wh[7]; const uint16_t* Wl[7];
    const float* bias[7];  void* C[7];
    int K[7], Mb[7], rowOff[7], bStride[7], mode[7];
    int blk0[8];
    int njobs;
};
// mode: 0 = fp32 out, 1 = tf32-rounded fp32 out, 2 = bf16 out, 4 = bf16 out scaled by EXP2C
__global__ __launch_bounds__(256, 2) void gemm_jobs(GJobs J) {
    extern __shared__ uint32_t smw[];
    int j = 0;
    while (j + 1 < J.njobs && (int)blockIdx.x >= J.blk0[j + 1]) ++j;
    const int lb = blockIdx.x - J.blk0[j];
    const uint16_t* __restrict__ Ah = J.Ah[j];
    const uint16_t* __restrict__ Al = J.Al[j];
    const uint16_t* __restrict__ Wh = J.Wh[j];
    const uint16_t* __restrict__ Wl = J.Wl[j];
    const float* __restrict__ bias = J.bias[j];
    void* Cv = J.C[j];
    const int K = J.K[j], Mb = J.Mb[j], rowOff = J.rowOff[j];
    const int bStride = J.bStride[j], mode = J.mode[j];

    const int tid = threadIdx.x, lane = tid & 31, wid = tid >> 5;
    const int wm = wid & 3, wn = wid >> 2;
    const int lr = lane >> 2, lc = lane & 3;
    const int m0 = (lb >> 3) * 128, n0 = (lb & 7) * 64;
    const int l16 = lane & 15, lh8 = (lane >> 4) << 3;

    float acc[2][4][4];
#pragma unroll
    for (int i = 0; i < 2; ++i)
#pragma unroll
        for (int jj = 0; jj < 4; ++jj)
#pragma unroll
            for (int e = 0; e < 4; ++e) acc[i][jj][e] = 0.f;

    const int nK = K >> 6;
    const uint32_t ub = smem_u32(smw);

#define STAGE(c, s) do { \
    const uint32_t d0 = ub + (s) * G_STW * 4; \
    _Pragma("unroll") \
    for (int it = 0; it < 4; ++it) { \
        int id = it * 256 + tid, row = id >> 3, seg = id & 7; \
        size_t so = (size_t)(m0 + row) * K + (c) * 64 + seg * 8; \
        uint32_t dw = (row * 36 + seg * 4) * 4; \
        CP16(d0 + dw, Ah + so); \
        CP16(d0 + G_OAL * 4 + dw, Al + so); \
    } \
    _Pragma("unroll") \
    for (int it = 0; it < 2; ++it) { \
        int id = it * 256 + tid, row = id >> 3, seg = id & 7; \
        size_t so = (size_t)((c) * 64 + row) * 512 + n0 + seg * 8; \
        uint32_t dw = (row * 36 + seg * 4) * 4; \
        CP16(d0 + G_OBH * 4 + dw, Wh + so); \
        CP16(d0 + G_OBL * 4 + dw, Wl + so); \
    } \
    CP_COMMIT(); \
} while (0)

    STAGE(0, 0);
    for (int c = 0; c < nK; ++c) {
        const int s = c & 1;
        if (c + 1 < nK) { STAGE(c + 1, s ^ 1); CP_WAIT(1); }
        else            { CP_WAIT(0); }
        __syncthreads();
        const uint32_t sb = ub + s * G_STW * 4;
#pragma unroll
        for (int st = 0; st < 4; ++st) {
            const int k0 = st * 16;
            uint32_t ah[2][4], al_[2][4], bh[2][4], bl_[2][4];
#pragma unroll
            for (int mf = 0; mf < 2; ++mf) {
                int row = wm * 32 + mf * 16 + l16;
                uint32_t ad = sb + (row * 36 + ((k0 + lh8) >> 1)) * 4;
                ldsm_x4(ah[mf], ad);
                ldsm_x4(al_[mf], ad + G_OAL * 4);
            }
#pragma unroll
            for (int p = 0; p < 2; ++p) {
                int row = k0 + l16;
                int col = wn * 32 + p * 16 + lh8;
                uint32_t bd = sb + (G_OBH + row * 36 + (col >> 1)) * 4;
                ldsm_x4_t(bh[p], bd);
                ldsm_x4_t(bl_[p], bd + (G_OBL - G_OBH) * 4);
            }
#pragma unroll
            for (int mf = 0; mf < 2; ++mf)
#pragma unroll
                for (int p = 0; p < 2; ++p) {
                    mma16(acc[mf][p * 2 + 0], ah[mf], &bh[p][0]);
                    mma16(acc[mf][p * 2 + 1], ah[mf], &bh[p][2]);
                }
#pragma unroll
            for (int mf = 0; mf < 2; ++mf)
#pragma unroll
                for (int p = 0; p < 2; ++p) {
                    mma16(acc[mf][p * 2 + 0], ah[mf], &bl_[p][0]);
                    mma16(acc[mf][p * 2 + 1], ah[mf], &bl_[p][2]);
                }
#pragma unroll
            for (int mf = 0; mf < 2; ++mf)
#pragma unroll
                for (int p = 0; p < 2; ++p) {
                    mma16(acc[mf][p * 2 + 0], al_[mf], &bh[p][0]);
                    mma16(acc[mf][p * 2 + 1], al_[mf], &bh[p][2]);
                }
        }
        __syncthreads();
    }
#undef STAGE
#pragma unroll
    for (int mf = 0; mf < 2; ++mf) {
        int r = m0 + wm * 32 + mf * 16 + lr;
        int b0i = r / Mb;
        size_t or0 = (size_t)b0i * bStride + rowOff + (r - b0i * Mb);
        int r2 = r + 8;
        int b1i = r2 / Mb;
        size_t or1 = (size_t)b1i * bStride + rowOff + (r2 - b1i * Mb);
#pragma unroll
        for (int nf = 0; nf < 4; ++nf) {
            int col = n0 + wn * 32 + nf * 8 + 2 * lc;
            float bv0 = bias[col], bv1 = bias[col + 1];
            float v00 = acc[mf][nf][0] + bv0, v01 = acc[mf][nf][1] + bv1;
            float v10 = acc[mf][nf][2] + bv0, v11 = acc[mf][nf][3] + bv1;
            if (mode >= 2) {
                if (mode == 4) { v00 *= EXP2C; v01 *= EXP2C; v10 *= EXP2C; v11 *= EXP2C; }
                uint16_t* Cb = (uint16_t*)Cv;
                *(uint32_t*)(Cb + or0 * 512 + col) = pkh(bf16_rn(v00), bf16_rn(v01));
                *(uint32_t*)(Cb + or1 * 512 + col) = pkh(bf16_rn(v10), bf16_rn(v11));
            } else {
                float* C = (float*)Cv;
                if (mode == 1) {
                    v00 = tf32_rn(v00); v01 = tf32_rn(v01);
                    v10 = tf32_rn(v10); v11 = tf32_rn(v11);
                }
                *(float2*)(C + or0 * 512 + col) = make_float2(v00, v01);
                *(float2*)(C + or1 * 512 + col) = make_float2(v10, v11);
            }
        }
    }
}

// ================= flash attention (R15 — best measured) =================
#define A_QW 0
#define A_KW 4608
#define A_VW 9216
#define A_PW 18432
#define A_MW 27136
#define A_LW 27648
#define A_TOTW 27904
#define AV 72

__global__ __launch_bounds__(256, 2) void attn_mma(
    const uint16_t* __restrict__ qb, const uint16_t* __restrict__ kb,
    const float* __restrict__ vb,
    uint16_t* __restrict__ oh, uint16_t* __restrict__ ol)
{
    extern __shared__ uint32_t smw[];
    float* smf = (float*)smw;
    uint32_t* sM = smw + A_MW;
    float* sP = smf + A_PW;      // fragment-major
    float* sL = smf + A_LW;
    const float4* PF = (const float4*)sP;

    const int tid = threadIdx.x, lane = tid & 31, wid = tid >> 5;
    const int wm = wid & 3, wn = wid >> 2;
    const int lr = lane >> 2, lc = lane & 3;
    const int ln8 = lane & 7;
    const int pair_bar_id = 1 + wm;
    const int q0 = blockIdx.x * 128, h = blockIdx.y, b = blockIdx.z;

    const uint16_t* Qg = qb + ((size_t)(b * 1024 + q0)) * 512 + h * 64;
    const uint16_t* Kg = kb + ((size_t)(b * 4096)) * 512 + h * 64;
    const float*    Vg = vb + ((size_t)(b * 4096)) * 512 + h * 64;
    const uint32_t* mbase = g_mbits + ((size_t)(b * 1024 + q0)) * 128;
    const uint32_t ubase = smem_u32(smw);
    const uint32_t uQ = ubase + A_QW * 4, uK = ubase + A_KW * 4;
    const uint32_t uV = ubase + A_VW * 4, uM = ubase + A_MW * 4;

#pragma unroll
    for (int it = 0; it < 4; ++it) {
        int id = it * 256 + tid, row = id >> 3, seg = id & 7;
        CP16(uQ + (row * 36 + seg * 4) * 4, Qg + (size_t)row * 512 + seg * 8);
    }
#pragma unroll
    for (int it = 0; it < 2; ++it) {
        int id = it * 256 + tid, row = id >> 3, seg = id & 7;
        CP16(uK + (row * 36 + seg * 4) * 4, Kg + (size_t)row * 512 + seg * 8);
    }
#pragma unroll
    for (int it = 0; it < 4; ++it) {
        int id = it * 256 + tid, row = id >> 4, seg = id & 15;
        CP16(uV + (row * AV + seg * 4) * 4, Vg + (size_t)row * 512 + seg * 4);
    }
    if (tid < 128) CP8(uM + tid * 8, (const char*)(mbase + (size_t)tid * 128));
    CP_COMMIT();
    CP_WAIT(0);
    __syncthreads();

    float o[2][4][4];
    float l_acc[2][2];
#pragma unroll
    for (int i = 0; i < 2; ++i) {
        l_acc[i][0] = 0.f; l_acc[i][1] = 0.f;
#pragma unroll
        for (int jj = 0; jj < 4; ++jj)
#pragma unroll
            for (int e = 0; e < 4; ++e) o[i][jj][e] = 0.f;
    }

    for (int t = 0; t < 64; ++t) {
        const int s = t & 1;
        if (t > 0) { CP_WAIT(0); __syncthreads(); }

        if (t < 63) {
            const uint16_t* Kn = Kg + (size_t)(t + 1) * 64 * 512;
            const float* Vn = Vg + (size_t)(t + 1) * 64 * 512;
            const uint32_t dK = uK + (s ^ 1) * 2304 * 4;
            const uint32_t dV = uV + (s ^ 1) * 64 * AV * 4;
#pragma unroll
            for (int it = 0; it < 2; ++it) {
                int id = it * 256 + tid, row = id >> 3, seg = id & 7;
                CP16(dK + (row * 36 + seg * 4) * 4, Kn + (size_t)row * 512 + seg * 8);
            }
#pragma unroll
            for (int it = 0; it < 4; ++it) {
                int id = it * 256 + tid, row = id >> 4, seg = id & 15;
                CP16(dV + (row * AV + seg * 4) * 4, Vn + (size_t)row * 512 + seg * 4);
            }
            if (tid < 128)
                CP8(uM + (s ^ 1) * 1024 + tid * 8,
                    (const char*)(mbase + (size_t)tid * 128 + (t + 1) * 2));
            CP_COMMIT();
        }

        // ---- S' = (Q*EXP2C) K^T ----
        const uint32_t uKs = uK + s * 2304 * 4;
        float sv[2][4][4];
#pragma unroll
        for (int i = 0; i < 2; ++i)
#pragma unroll
            for (int jj = 0; jj < 4; ++jj)
#pragma unroll
                for (int e = 0; e < 4; ++e) sv[i][jj][e] = 0.f;
#pragma unroll
        for (int ks = 0; ks < 4; ++ks) {
            int kcb = ks * 16 + ((lane >> 3) & 1) * 8;
            int nrow = wn * 32 + (lane >> 4) * 8 + ln8;
            uint32_t bk0[4], bk1[4];
            ldsm_x4(bk0, uKs + (nrow * 36 + (kcb >> 1)) * 4);
            ldsm_x4(bk1, uKs + ((nrow + 16) * 36 + (kcb >> 1)) * 4);
#pragma unroll
            for (int mf = 0; mf < 2; ++mf) {
                int qrow = wm * 32 + mf * 16 + ((lane >> 3) & 1) * 8 + ln8;
                int kc = ks * 16 + (lane >> 4) * 8;
                uint32_t aq[4];
                ldsm_x4(aq, uQ + (qrow * 36 + (kc >> 1)) * 4);
                mma16(sv[mf][0], aq, &bk0[0]);
                mma16(sv[mf][1], aq, &bk0[2]);
                mma16(sv[mf][2], aq, &bk1[0]);
                mma16(sv[mf][3], aq, &bk1[2]);
            }
        }

        // ---- masked no-max softmax + fragment-major P write (fp32 P; HW tf32-truncates) ----
#pragma unroll
        for (int mf = 0; mf < 2; ++mf)
#pragma unroll
            for (int u = 0; u < 2; ++u) {
                int row = wm * 32 + mf * 16 + lr + u * 8;
                uint32_t mw = sM[s * 256 + row * 2 + wn];
                float rs = 0.f;
#pragma unroll
                for (int nf = 0; nf < 4; ++nf) {
#pragma unroll
                    for (int q2 = 0; q2 < 2; ++q2) {
                        int cr = u * 2 + q2;
                        int cl = nf * 8 + 2 * lc + q2;
                        float p = ex2f(sv[mf][nf][cr]);
                        p = ((mw >> cl) & 1u) ? p : 0.f;
                        rs += p;
                        sv[mf][nf][cr] = p;
                    }
                }
                l_acc[mf][u] += rs;
                int gbase = (((wm * 2 + mf) * 8 + wn * 4) * 8 + lr) * 16 + u + 2 * (lc >> 1);
                int c0 = (lc & 1) * 8;
#pragma unroll
                for (int nf = 0; nf < 4; ++nf) {
                    sP[gbase + nf * 128 + c0]     = sv[mf][nf][u * 2];
                    sP[gbase + nf * 128 + c0 + 4] = sv[mf][nf][u * 2 + 1];
                }
            }
        PAIR_BAR(pair_bar_id);

        // ---- O += P @ V ----
        const uint32_t* sVu = smw + A_VW + s * 64 * AV;
#pragma unroll
        for (int ks = 0; ks < 8; ++ks) {
            const int kb0 = ks * 8;
            uint32_t bv[4][2];
#pragma unroll
            for (int nf = 0; nf < 4; ++nf) {
                int drow = wn * 32 + nf * 8 + lr;
                bv[nf][0] = sVu[(kb0 + lc) * AV + drow];
                bv[nf][1] = sVu[(kb0 + 4 + lc) * AV + drow];
            }
#pragma unroll
            for (int mf = 0; mf < 2; ++mf) {
                float4 av = PF[(((wm * 2 + mf) * 8 + ks) * 8 + lr) * 4 + lc];
                uint32_t ap[4] = {__float_as_uint(av.x), __float_as_uint(av.y),
                                  __float_as_uint(av.z), __float_as_uint(av.w)};
#pragma unroll
                for (int nf = 0; nf < 4; ++nf) mma8(o[mf][nf], ap, bv[nf]);
            }
        }
    }

#pragma unroll
    for (int mf = 0; mf < 2; ++mf)
#pragma unroll
        for (int u = 0; u < 2; ++u) {
            float v = l_acc[mf][u];
            v += __shfl_xor_sync(0xffffffffu, v, 1);
            v += __shfl_xor_sync(0xffffffffu, v, 2);
            l_acc[mf][u] = v;
        }
    if (lc == 0) {
#pragma unroll
        for (int mf = 0; mf < 2; ++mf)
#pragma unroll
            for (int u = 0; u < 2; ++u)
                sL[wn * 128 + wm * 32 + mf * 16 + lr + u * 8] = l_acc[mf][u];
    }
    __syncthreads();

    uint16_t* Oh = oh + ((size_t)(b * 1024 + q0)) * 512 + h * 64;
    uint16_t* Ol = ol + ((size_t)(b * 1024 + q0)) * 512 + h * 64;
#pragma unroll
    for (int mf = 0; mf < 2; ++mf)
#pragma unroll
        for (int u = 0; u < 2; ++u) {
            int row = wm * 32 + mf * 16 + lr + u * 8;
            float linv = 1.f / (sL[row] + sL[128 + row]);
#pragma unroll
            for (int nf = 0; nf < 4; ++nf) {
                int col = wn * 32 + nf * 8 + 2 * lc;
                float v0 = o[mf][nf][u * 2] * linv;
                float v1 = o[mf][nf][u * 2 + 1] * linv;
                float h0 = bf16_rn(v0), h1 = bf16_rn(v1);
                *(uint32_t*)(Oh + (size_t)row * 512 + col) = pkh(h0, h1);
                *(uint32_t*)(Ol + (size_t)row * 512 + col) = bf2(v0 - h0, v1 - h1);
            }
        }
}

// ================= launcher =================
extern "C" void kernel_launch(void* const* d_in, const int* in_sizes, int n_in,
                              void* d_out, int out_size) {
    const float* x        = (const float*)d_in[0];
    const float* context  = (const float*)d_in[1];
    const float* context2 = (const float*)d_in[2];
    const float* context3 = (const float*)d_in[3];
    const void*  mask1 = d_in[4];
    const void*  mask2 = d_in[5];
    const void*  mask3 = d_in[6];
    const float* bq  = (const float*)d_in[8];
    const float* bk1 = (const float*)d_in[10];
    const float* bv1 = (const float*)d_in[12];
    const float* bk2 = (const float*)d_in[14];
    const float* bv2 = (const float*)d_in[16];
    const float* bk3 = (const float*)d_in[18];
    const float* bv3 = (const float*)d_in[20];
    const float* Wo  = (const float*)d_in[21];
    const float* bo  = (const float*)d_in[22];
    float* out = (float*)d_out;

    uint16_t *hp, *lp, *qbp, *kbp;
    float *vp;
    cudaGetSymbolAddress((void**)&hp,  g_h);
    cudaGetSymbolAddress((void**)&lp,  g_l);
    cudaGetSymbolAddress((void**)&qbp, g_qb);
    cudaGetSymbolAddress((void**)&kbp, g_kb);
    cudaGetSymbolAddress((void**)&vp,  g_v);

    const int smem_gemm = 2 * G_STW * 4;
    const int smem_attn = A_TOTW * 4;
    static bool once = false;
    static cudaStream_t s2;
    static cudaEvent_t ev1, ev2;
    if (!once) {
        cudaFuncSetAttribute(gemm_jobs, cudaFuncAttributeMaxDynamicSharedMemorySize, smem_gemm);
        cudaFuncSetAttribute(attn_mma, cudaFuncAttributeMaxDynamicSharedMemorySize, smem_attn);
        cudaStreamCreateWithFlags(&s2, cudaStreamNonBlocking);
        cudaEventCreateWithFlags(&ev1, cudaEventDisableTiming);
        cudaEventCreateWithFlags(&ev2, cudaEventDisableTiming);
        once = true;
    }

    cudaEventRecord(ev1, 0);
    cudaStreamWaitEvent(s2, ev1, 0);
    detect_mask_kernel<<<1, 256, 0, s2>>>((const unsigned char*)mask1);
    pack_mask_kernel<<<2048, 256, 0, s2>>>(mask1, mask2, mask3);
    cudaEventRecord(ev2, s2);

    {
        SplitJobs js;
        const float* srcs[12] = {x, context, context2, context3,
                                 (const float*)d_in[7], (const float*)d_in[9],
                                 (const float*)d_in[11], (const float*)d_in[13],
                                 (const float*)d_in[15], (const float*)d_in[17],
                                 (const float*)d_in[19], Wo};
        int offs[12] = {OFF_X, OFF_C1, OFF_C2, OFF_C3,
                        OFF_WQ, OFF_WK1, OFF_WV1, OFF_WK2, OFF_WV2,
                        OFF_WK3, OFF_WV3, OFF_WO};
        int cnts[12] = {512, 512, 768, 512, 64, 64, 64, 96, 96, 32, 32, 64};
        int cum = 0;
        for (int i = 0; i < 12; ++i) {
            js.src[i] = srcs[i]; js.off[i] = offs[i];
            js.nblk[i] = cum; cum += cnts[i];
        }
        js.nblk[12] = cum;
        split_kernel<<<cum, 256>>>(js, 12);
    }

    {
        GJobs J;
        int aoffs[7]  = {OFF_X, OFF_C1, OFF_C2, OFF_C3, OFF_C1, OFF_C2, OFF_C3};
        int woffs[7]  = {OFF_WQ, OFF_WK1, OFF_WK2, OFF_WK3, OFF_WV1, OFF_WV2, OFF_WV3};
        const float* biases[7] = {bq, bk1, bk2, bk3, bv1, bv2, bv3};
        void* Cs[7]   = {qbp, kbp, kbp, kbp, vp, vp, vp};
        int Ks[7]     = {512, 512, 768, 256, 512, 768, 256};
        int Mbs[7]    = {1024, 1024, 1024, 2048, 1024, 1024, 2048};
        int ros[7]    = {0, 0, 1024, 2048, 0, 1024, 2048};
        int bss[7]    = {1024, 4096, 4096, 4096, 4096, 4096, 4096};
        int modes[7]  = {4, 2, 2, 2, 1, 1, 1};
        int blks[7]   = {256, 256, 256, 512, 256, 256, 512};
        int cum = 0;
        for (int i = 0; i < 7; ++i) {
            J.Ah[i] = hp + aoffs[i]; J.Al[i] = lp + aoffs[i];
            J.Wh[i] = hp + woffs[i]; J.Wl[i] = lp + woffs[i];
            J.bias[i] = biases[i]; J.C[i] = Cs[i];
            J.K[i] = Ks[i]; J.Mb[i] = Mbs[i]; J.rowOff[i] = ros[i];
            J.bStride[i] = bss[i]; J.mode[i] = modes[i];
            J.blk0[i] = cum; cum += blks[i];
        }
        J.blk0[7] = cum; J.njobs = 7;
        gemm_jobs<<<cum, 256, smem_gemm>>>(J);
    }

    cudaStreamWaitEvent(0, ev2, 0);

    attn_mma<<<dim3(8, 8, 4), 256, smem_attn>>>(qbp, kbp, vp, hp + OFF_AO, lp + OFF_AO);

    {
        GJobs J;
        J.Ah[0] = hp + OFF_AO; J.Al[0] = lp + OFF_AO;
        J.Wh[0] = hp + OFF_WO; J.Wl[0] = lp + OFF_WO;
        J.bias[0] = bo; J.C[0] = out;
        J.K[0] = 512; J.Mb[0] = 1024; J.rowOff[0] = 0;
        J.bStride[0] = 1024; J.mode[0] = 0;
        J.blk0[0] = 0; J.blk0[1] = 256; J.njobs = 1;
        gemm_jobs<<<256, 256, smem_gemm>>>(J);
    }
}

// round 17
// speedup vs baseline: 1.0425x; 1.0046x over previous
#include <cuda_runtime.h>
#include <cstdint>

#define EXP2C 0.1803368801111204f   /* (1/8) * log2(e) */

// ================= pools / scratch =================
#define OFF_X   0
#define OFF_C1  2097152
#define OFF_C2  4194304
#define OFF_C3  7340032
#define OFF_AO  9437184
#define OFF_WQ  11534336
#define OFF_WK1 11796480
#define OFF_WV1 12058624
#define OFF_WK2 12320768
#define OFF_WV2 12713984
#define OFF_WK3 13107200
#define OFF_WV3 13238272
#define OFF_WO  13369344
#define POOL_N  13631488

__device__ uint16_t g_h[POOL_N];
__device__ uint16_t g_l[POOL_N];
__device__ uint16_t g_qb[4 * 1024 * 512];
__device__ uint16_t g_kb[4 * 4096 * 512];
__device__ float    g_v[4 * 4096 * 512];
__device__ uint32_t g_mbits[4 * 1024 * 128];
__device__ int      g_mask_is_byte;

// ================= helpers =================
__device__ __forceinline__ uint32_t smem_u32(const void* p) {
    uint32_t a;
    asm("{ .reg .u64 t; cvta.to.shared.u64 t, %1; cvt.u32.u64 %0, t; }" : "=r"(a) : "l"(p));
    return a;
}
#define CP16(dst, src) \
    asm volatile("cp.async.cg.shared.global [%0], [%1], 16;" :: "r"(dst), "l"(src))
#define CP8(dst, src) \
    asm volatile("cp.async.ca.shared.global [%0], [%1], 8;" :: "r"(dst), "l"(src))
#define CP_COMMIT() asm volatile("cp.async.commit_group;" ::: "memory")
#define CP_WAIT(n)  asm volatile("cp.async.wait_group %0;" :: "n"(n) : "memory")
#define PAIR_BAR(id) \
    asm volatile("bar.sync %0, 64;" :: "r"(id) : "memory")

__device__ __forceinline__ float tf32_rn(float x) {
    return __uint_as_float((__float_as_uint(x) + 0x1000u) & 0xFFFFE000u);
}
__device__ __forceinline__ float bf16_rn(float x) {
    uint32_t u = __float_as_uint(x);
    u += 0x7FFFu + ((u >> 16) & 1u);
    return __uint_as_float(u & 0xFFFF0000u);
}
__device__ __forceinline__ uint32_t pkh(float a, float b) {
    return (__float_as_uint(b) & 0xFFFF0000u) | (__float_as_uint(a) >> 16);
}
__device__ __forceinline__ uint32_t bf2(float a, float b) {
    uint32_t r;
    asm("cvt.rn.bf16x2.f32 %0, %1, %2;" : "=r"(r) : "f"(b), "f"(a));
    return r;
}
__device__ __forceinline__ float ex2f(float y) {
    float r;
    asm("ex2.approx.f32 %0, %1;" : "=f"(r) : "f"(y));
    return r;
}
__device__ __forceinline__ void mma8(float* c, const uint32_t* a, const uint32_t* b) {
    asm volatile("mma.sync.aligned.m16n8k8.row.col.f32.tf32.tf32.f32 "
        "{%0,%1,%2,%3},{%4,%5,%6,%7},{%8,%9},{%0,%1,%2,%3};"
        : "+f"(c[0]), "+f"(c[1]), "+f"(c[2]), "+f"(c[3])
        : "r"(a[0]), "r"(a[1]), "r"(a[2]), "r"(a[3]), "r"(b[0]), "r"(b[1]));
}
__device__ __forceinline__ void mma16(float* c, const uint32_t* a, const uint32_t* b) {
    asm volatile("mma.sync.aligned.m16n8k16.row.col.f32.bf16.bf16.f32 "
        "{%0,%1,%2,%3},{%4,%5,%6,%7},{%8,%9},{%0,%1,%2,%3};"
        : "+f"(c[0]), "+f"(c[1]), "+f"(c[2]), "+f"(c[3])
        : "r"(a[0]), "r"(a[1]), "r"(a[2]), "r"(a[3]), "r"(b[0]), "r"(b[1]));
}
__device__ __forceinline__ void ldsm_x4(uint32_t* r, uint32_t addr) {
    asm volatile("ldmatrix.sync.aligned.m8n8.x4.shared.b16 {%0,%1,%2,%3}, [%4];"
        : "=r"(r[0]), "=r"(r[1]), "=r"(r[2]), "=r"(r[3]) : "r"(addr));
}
__device__ __forceinline__ void ldsm_x4_t(uint32_t* r, uint32_t addr) {
    asm volatile("ldmatrix.sync.aligned.m8n8.x4.trans.shared.b16 {%0,%1,%2,%3}, [%4];"
        : "=r"(r[0]), "=r"(r[1]), "=r"(r[2]), "=r"(r[3]) : "r"(addr));
}

// ================= mask detect + bit-pack =================
__global__ void detect_mask_kernel(const unsigned char* __restrict__ m) {
    __shared__ int any;
    if (threadIdx.x == 0) any = 0;
    __syncthreads();
    int found = 0;
    for (int i = threadIdx.x; i < 4096; i += blockDim.x)
        if ((i & 3) == 1 && m[i]) found = 1;
    if (found) atomicOr(&any, 1);
    __syncthreads();
    if (threadIdx.x == 0) g_mask_is_byte = any;
}

__global__ void pack_mask_kernel(const void* __restrict__ m1, const void* __restrict__ m2,
                                 const void* __restrict__ m3) {
    int idx = blockIdx.x * blockDim.x + threadIdx.x;
    if (idx >= 4 * 1024 * 128) return;
    int w = idx & 127, q = (idx >> 7) & 1023, b = idx >> 17;
    int k0 = w * 32;
    const void* mp; int nseg, jl;
    if (k0 < 1024)      { mp = m1; nseg = 1024; jl = k0; }
    else if (k0 < 2048) { mp = m2; nseg = 1024; jl = k0 - 1024; }
    else                { mp = m3; nseg = 2048; jl = k0 - 2048; }
    size_t base = (size_t)(b * 1024 + q) * nseg + jl;
    uint32_t bits = 0;
    if (g_mask_is_byte) {
        const uint4* p = (const uint4*)((const unsigned char*)mp + base);
        uint4 a = p[0], c = p[1];
        uint32_t ws[8] = {a.x, a.y, a.z, a.w, c.x, c.y, c.z, c.w};
#pragma unroll
        for (int wi = 0; wi < 8; ++wi)
#pragma unroll
            for (int by = 0; by < 4; ++by)
                if ((ws[wi] >> (8 * by)) & 0xFFu) bits |= 1u << (wi * 4 + by);
    } else {
        const uint4* p = (const uint4*)((const uint32_t*)mp + base);
#pragma unroll
        for (int wi = 0; wi < 8; ++wi) {
            uint4 v = p[wi];
            if (v.x) bits |= 1u << (wi * 4 + 0);
            if (v.y) bits |= 1u << (wi * 4 + 1);
            if (v.z) bits |= 1u << (wi * 4 + 2);
            if (v.w) bits |= 1u << (wi * 4 + 3);
        }
    }
    g_mbits[idx] = bits;
}

// ================= bf16 hi/lo split (pre-pass) =================
struct SplitJobs {
    const float* src[12];
    int nblk[13];
    int off[12];
};
__global__ __launch_bounds__(256) void split_kernel(SplitJobs j, int njobs) {
    int bid = blockIdx.x;
    int ji = 0;
    while (ji + 1 < njobs && bid >= j.nblk[ji + 1]) ++ji;
    int local = bid - j.nblk[ji];
    const float4* src = (const float4*)j.src[ji];
    uint2* dh = (uint2*)(g_h + j.off[ji]);
    uint2* dl = (uint2*)(g_l + j.off[ji]);
    size_t base4 = (size_t)local * 1024;
#pragma unroll
    for (int it = 0; it < 4; ++it) {
        size_t i4 = base4 + it * 256 + threadIdx.x;
        float4 v = src[i4];
        float h0 = bf16_rn(v.x), h1 = bf16_rn(v.y), h2 = bf16_rn(v.z), h3 = bf16_rn(v.w);
        dh[i4] = make_uint2(pkh(h0, h1), pkh(h2, h3));
        dl[i4] = make_uint2(bf2(v.x - h0, v.y - h1), bf2(v.z - h2, v.w - h3));
    }
}

// ================= 3xBF16 HMMA GEMM (measured-best loop; shift-based row remap) =================
#define G_OAL 4608
#define G_OBH 9216
#define G_OBL 11520
#define G_STW 13824
struct GJobs {
    const uint16_t* Ah[7]; const uint16_t* Al[7];
    const uint16_t* Wh[7]; const uint16_t* Wl[7];
    const float* bias[7];  void* C[7];
    int K[7], mbShift[7], rowOff[7], bStride[7], mode[7];   // Mb = 1 << mbShift
    int blk0[8];
    int njobs;
};
// mode: 0 = fp32 out, 1 = tf32-rounded fp32 out, 2 = bf16 out, 4 = bf16 out scaled by EXP2C
__global__ __launch_bounds__(256, 2) void gemm_jobs(GJobs J) {
    extern __shared__ uint32_t smw[];
    int j = 0;
    while (j + 1 < J.njobs && (int)blockIdx.x >= J.blk0[j + 1]) ++j;
    const int lb = blockIdx.x - J.blk0[j];
    const uint16_t* __restrict__ Ah = J.Ah[j];
    const uint16_t* __restrict__ Al = J.Al[j];
    const uint16_t* __restrict__ Wh = J.Wh[j];
    const uint16_t* __restrict__ Wl = J.Wl[j];
    const float* __restrict__ bias = J.bias[j];
    void* Cv = J.C[j];
    const int K = J.K[j], mbS = J.mbShift[j], rowOff = J.rowOff[j];
    const int bStride = J.bStride[j], mode = J.mode[j];
    const int mbMask = (1 << mbS) - 1;

    const int tid = threadIdx.x, lane = tid & 31, wid = tid >> 5;
    const int wm = wid & 3, wn = wid >> 2;
    const int lr = lane >> 2, lc = lane & 3;
    const int m0 = (lb >> 3) * 128, n0 = (lb & 7) * 64;
    const int l16 = lane & 15, lh8 = (lane >> 4) << 3;

    float acc[2][4][4];
#pragma unroll
    for (int i = 0; i < 2; ++i)
#pragma unroll
        for (int jj = 0; jj < 4; ++jj)
#pragma unroll
            for (int e = 0; e < 4; ++e) acc[i][jj][e] = 0.f;

    const int nK = K >> 6;
    const uint32_t ub = smem_u32(smw);

#define STAGE(c, s) do { \
    const uint32_t d0 = ub + (s) * G_STW * 4; \
    _Pragma("unroll") \
    for (int it = 0; it < 4; ++it) { \
        int id = it * 256 + tid, row = id >> 3, seg = id & 7; \
        size_t so = (size_t)(m0 + row) * K + (c) * 64 + seg * 8; \
        uint32_t dw = (row * 36 + seg * 4) * 4; \
        CP16(d0 + dw, Ah + so); \
        CP16(d0 + G_OAL * 4 + dw, Al + so); \
    } \
    _Pragma("unroll") \
    for (int it = 0; it < 2; ++it) { \
        int id = it * 256 + tid, row = id >> 3, seg = id & 7; \
        size_t so = (size_t)((c) * 64 + row) * 512 + n0 + seg * 8; \
        uint32_t dw = (row * 36 + seg * 4) * 4; \
        CP16(d0 + G_OBH * 4 + dw, Wh + so); \
        CP16(d0 + G_OBL * 4 + dw, Wl + so); \
    } \
    CP_COMMIT(); \
} while (0)

    STAGE(0, 0);
    for (int c = 0; c < nK; ++c) {
        const int s = c & 1;
        if (c + 1 < nK) { STAGE(c + 1, s ^ 1); CP_WAIT(1); }
        else            { CP_WAIT(0); }
        __syncthreads();
        const uint32_t sb = ub + s * G_STW * 4;
#pragma unroll
        for (int st = 0; st < 4; ++st) {
            const int k0 = st * 16;
            uint32_t ah[2][4], al_[2][4], bh[2][4], bl_[2][4];
#pragma unroll
            for (int mf = 0; mf < 2; ++mf) {
                int row = wm * 32 + mf * 16 + l16;
                uint32_t ad = sb + (row * 36 + ((k0 + lh8) >> 1)) * 4;
                ldsm_x4(ah[mf], ad);
                ldsm_x4(al_[mf], ad + G_OAL * 4);
            }
#pragma unroll
            for (int p = 0; p < 2; ++p) {
                int row = k0 + l16;
                int col = wn * 32 + p * 16 + lh8;
                uint32_t bd = sb + (G_OBH + row * 36 + (col >> 1)) * 4;
                ldsm_x4_t(bh[p], bd);
                ldsm_x4_t(bl_[p], bd + (G_OBL - G_OBH) * 4);
            }
#pragma unroll
            for (int mf = 0; mf < 2; ++mf)
#pragma unroll
                for (int p = 0; p < 2; ++p) {
                    mma16(acc[mf][p * 2 + 0], ah[mf], &bh[p][0]);
                    mma16(acc[mf][p * 2 + 1], ah[mf], &bh[p][2]);
                }
#pragma unroll
            for (int mf = 0; mf < 2; ++mf)
#pragma unroll
                for (int p = 0; p < 2; ++p) {
                    mma16(acc[mf][p * 2 + 0], ah[mf], &bl_[p][0]);
                    mma16(acc[mf][p * 2 + 1], ah[mf], &bl_[p][2]);
                }
#pragma unroll
            for (int mf = 0; mf < 2; ++mf)
#pragma unroll
                for (int p = 0; p < 2; ++p) {
                    mma16(acc[mf][p * 2 + 0], al_[mf], &bh[p][0]);
                    mma16(acc[mf][p * 2 + 1], al_[mf], &bh[p][2]);
                }
        }
        __syncthreads();
    }
#undef STAGE
#pragma unroll
    for (int mf = 0; mf < 2; ++mf) {
        int r = m0 + wm * 32 + mf * 16 + lr;
        size_t or0 = (size_t)(r >> mbS) * bStride + rowOff + (r & mbMask);
        int r2 = r + 8;
        size_t or1 = (size_t)(r2 >> mbS) * bStride + rowOff + (r2 & mbMask);
#pragma unroll
        for (int nf = 0; nf < 4; ++nf) {
            int col = n0 + wn * 32 + nf * 8 + 2 * lc;
            float bv0 = bias[col], bv1 = bias[col + 1];
            float v00 = acc[mf][nf][0] + bv0, v01 = acc[mf][nf][1] + bv1;
            float v10 = acc[mf][nf][2] + bv0, v11 = acc[mf][nf][3] + bv1;
            if (mode >= 2) {
                if (mode == 4) { v00 *= EXP2C; v01 *= EXP2C; v10 *= EXP2C; v11 *= EXP2C; }
                uint16_t* Cb = (uint16_t*)Cv;
                *(uint32_t*)(Cb + or0 * 512 + col) = pkh(bf16_rn(v00), bf16_rn(v01));
                *(uint32_t*)(Cb + or1 * 512 + col) = pkh(bf16_rn(v10), bf16_rn(v11));
            } else {
                float* C = (float*)Cv;
                if (mode == 1) {
                    v00 = tf32_rn(v00); v01 = tf32_rn(v01);
                    v10 = tf32_rn(v10); v11 = tf32_rn(v11);
                }
                *(float2*)(C + or0 * 512 + col) = make_float2(v00, v01);
                *(float2*)(C + or1 * 512 + col) = make_float2(v10, v11);
            }
        }
    }
}

// ================= flash attention (measured-best) =================
#define A_QW 0
#define A_KW 4608
#define A_VW 9216
#define A_PW 18432
#define A_MW 27136
#define A_LW 27648
#define A_TOTW 27904
#define AV 72

__global__ __launch_bounds__(256, 2) void attn_mma(
    const uint16_t* __restrict__ qb, const uint16_t* __restrict__ kb,
    const float* __restrict__ vb,
    uint16_t* __restrict__ oh, uint16_t* __restrict__ ol)
{
    extern __shared__ uint32_t smw[];
    float* smf = (float*)smw;
    uint32_t* sM = smw + A_MW;
    float* sP = smf + A_PW;      // fragment-major
    float* sL = smf + A_LW;
    const float4* PF = (const float4*)sP;

    const int tid = threadIdx.x, lane = tid & 31, wid = tid >> 5;
    const int wm = wid & 3, wn = wid >> 2;
    const int lr = lane >> 2, lc = lane & 3;
    const int ln8 = lane & 7;
    const int pair_bar_id = 1 + wm;
    const int q0 = blockIdx.x * 128, h = blockIdx.y, b = blockIdx.z;

    const uint16_t* Qg = qb + ((size_t)(b * 1024 + q0)) * 512 + h * 64;
    const uint16_t* Kg = kb + ((size_t)(b * 4096)) * 512 + h * 64;
    const float*    Vg = vb + ((size_t)(b * 4096)) * 512 + h * 64;
    const uint32_t* mbase = g_mbits + ((size_t)(b * 1024 + q0)) * 128;
    const uint32_t ubase = smem_u32(smw);
    const uint32_t uQ = ubase + A_QW * 4, uK = ubase + A_KW * 4;
    const uint32_t uV = ubase + A_VW * 4, uM = ubase + A_MW * 4;

#pragma unroll
    for (int it = 0; it < 4; ++it) {
        int id = it * 256 + tid, row = id >> 3, seg = id & 7;
        CP16(uQ + (row * 36 + seg * 4) * 4, Qg + (size_t)row * 512 + seg * 8);
    }
#pragma unroll
    for (int it = 0; it < 2; ++it) {
        int id = it * 256 + tid, row = id >> 3, seg = id & 7;
        CP16(uK + (row * 36 + seg * 4) * 4, Kg + (size_t)row * 512 + seg * 8);
    }
#pragma unroll
    for (int it = 0; it < 4; ++it) {
        int id = it * 256 + tid, row = id >> 4, seg = id & 15;
        CP16(uV + (row * AV + seg * 4) * 4, Vg + (size_t)row * 512 + seg * 4);
    }
    if (tid < 128) CP8(uM + tid * 8, (const char*)(mbase + (size_t)tid * 128));
    CP_COMMIT();
    CP_WAIT(0);
    __syncthreads();

    float o[2][4][4];
    float l_acc[2][2];
#pragma unroll
    for (int i = 0; i < 2; ++i) {
        l_acc[i][0] = 0.f; l_acc[i][1] = 0.f;
#pragma unroll
        for (int jj = 0; jj < 4; ++jj)
#pragma unroll
            for (int e = 0; e < 4; ++e) o[i][jj][e] = 0.f;
    }

    for (int t = 0; t < 64; ++t) {
        const int s = t & 1;
        if (t > 0) { CP_WAIT(0); __syncthreads(); }

        if (t < 63) {
            const uint16_t* Kn = Kg + (size_t)(t + 1) * 64 * 512;
            const float* Vn = Vg + (size_t)(t + 1) * 64 * 512;
            const uint32_t dK = uK + (s ^ 1) * 2304 * 4;
            const uint32_t dV = uV + (s ^ 1) * 64 * AV * 4;
#pragma unroll
            for (int it = 0; it < 2; ++it) {
                int id = it * 256 + tid, row = id >> 3, seg = id & 7;
                CP16(dK + (row * 36 + seg * 4) * 4, Kn + (size_t)row * 512 + seg * 8);
            }
#pragma unroll
            for (int it = 0; it < 4; ++it) {
                int id = it * 256 + tid, row = id >> 4, seg = id & 15;
                CP16(dV + (row * AV + seg * 4) * 4, Vn + (size_t)row * 512 + seg * 4);
            }
            if (tid < 128)
                CP8(uM + (s ^ 1) * 1024 + tid * 8,
                    (const char*)(mbase + (size_t)tid * 128 + (t + 1) * 2));
            CP_COMMIT();
        }

        // ---- S' = (Q*EXP2C) K^T ----
        const uint32_t uKs = uK + s * 2304 * 4;
        float sv[2][4][4];
#pragma unroll
        for (int i = 0; i < 2; ++i)
#pragma unroll
            for (int jj = 0; jj < 4; ++jj)
#pragma unroll
                for (int e = 0; e < 4; ++e) sv[i][jj][e] = 0.f;
#pragma unroll
        for (int ks = 0; ks < 4; ++ks) {
            int kcb = ks * 16 + ((lane >> 3) & 1) * 8;
            int nrow = wn * 32 + (lane >> 4) * 8 + ln8;
            uint32_t bk0[4], bk1[4];
            ldsm_x4(bk0, uKs + (nrow * 36 + (kcb >> 1)) * 4);
            ldsm_x4(bk1, uKs + ((nrow + 16) * 36 + (kcb >> 1)) * 4);
#pragma unroll
            for (int mf = 0; mf < 2; ++mf) {
                int qrow = wm * 32 + mf * 16 + ((lane >> 3) & 1) * 8 + ln8;
                int kc = ks * 16 + (lane >> 4) * 8;
                uint32_t aq[4];
                ldsm_x4(aq, uQ + (qrow * 36 + (kc >> 1)) * 4);
                mma16(sv[mf][0], aq, &bk0[0]);
                mma16(sv[mf][1], aq, &bk0[2]);
                mma16(sv[mf][2], aq, &bk1[0]);
                mma16(sv[mf][3], aq, &bk1[2]);
            }
        }

        // ---- masked no-max softmax + fragment-major P write ----
#pragma unroll
        for (int mf = 0; mf < 2; ++mf)
#pragma unroll
            for (int u = 0; u < 2; ++u) {
                int row = wm * 32 + mf * 16 + lr + u * 8;
                uint32_t mw = sM[s * 256 + row * 2 + wn];
                float rs = 0.f;
#pragma unroll
                for (int nf = 0; nf < 4; ++nf) {
#pragma unroll
                    for (int q2 = 0; q2 < 2; ++q2) {
                        int cr = u * 2 + q2;
                        int cl = nf * 8 + 2 * lc + q2;
                        float p = ex2f(sv[mf][nf][cr]);
                        p = ((mw >> cl) & 1u) ? p : 0.f;
                        rs += p;
                        sv[mf][nf][cr] = p;
                    }
                }
                l_acc[mf][u] += rs;
                int gbase = (((wm * 2 + mf) * 8 + wn * 4) * 8 + lr) * 16 + u + 2 * (lc >> 1);
                int c0 = (lc & 1) * 8;
#pragma unroll
                for (int nf = 0; nf < 4; ++nf) {
                    sP[gbase + nf * 128 + c0]     = sv[mf][nf][u * 2];
                    sP[gbase + nf * 128 + c0 + 4] = sv[mf][nf][u * 2 + 1];
                }
            }
        PAIR_BAR(pair_bar_id);

        // ---- O += P @ V ----
        const uint32_t* sVu = smw + A_VW + s * 64 * AV;
#pragma unroll
        for (int ks = 0; ks < 8; ++ks) {
            const int kb0 = ks * 8;
            uint32_t bv[4][2];
#pragma unroll
            for (int nf = 0; nf < 4; ++nf) {
                int drow = wn * 32 + nf * 8 + lr;
                bv[nf][0] = sVu[(kb0 + lc) * AV + drow];
                bv[nf][1] = sVu[(kb0 + 4 + lc) * AV + drow];
            }
#pragma unroll
            for (int mf = 0; mf < 2; ++mf) {
                float4 av = PF[(((wm * 2 + mf) * 8 + ks) * 8 + lr) * 4 + lc];
                uint32_t ap[4] = {__float_as_uint(av.x), __float_as_uint(av.y),
                                  __float_as_uint(av.z), __float_as_uint(av.w)};
#pragma unroll
                for (int nf = 0; nf < 4; ++nf) mma8(o[mf][nf], ap, bv[nf]);
            }
        }
    }

#pragma unroll
    for (int mf = 0; mf < 2; ++mf)
#pragma unroll
        for (int u = 0; u < 2; ++u) {
            float v = l_acc[mf][u];
            v += __shfl_xor_sync(0xffffffffu, v, 1);
            v += __shfl_xor_sync(0xffffffffu, v, 2);
            l_acc[mf][u] = v;
        }
    if (lc == 0) {
#pragma unroll
        for (int mf = 0; mf < 2; ++mf)
#pragma unroll
            for (int u = 0; u < 2; ++u)
                sL[wn * 128 + wm * 32 + mf * 16 + lr + u * 8] = l_acc[mf][u];
    }
    __syncthreads();

    uint16_t* Oh = oh + ((size_t)(b * 1024 + q0)) * 512 + h * 64;
    uint16_t* Ol = ol + ((size_t)(b * 1024 + q0)) * 512 + h * 64;
#pragma unroll
    for (int mf = 0; mf < 2; ++mf)
#pragma unroll
        for (int u = 0; u < 2; ++u) {
            int row = wm * 32 + mf * 16 + lr + u * 8;
            float linv = 1.f / (sL[row] + sL[128 + row]);
#pragma unroll
            for (int nf = 0; nf < 4; ++nf) {
                int col = wn * 32 + nf * 8 + 2 * lc;
                float v0 = o[mf][nf][u * 2] * linv;
                float v1 = o[mf][nf][u * 2 + 1] * linv;
                float h0 = bf16_rn(v0), h1 = bf16_rn(v1);
                *(uint32_t*)(Oh + (size_t)row * 512 + col) = pkh(h0, h1);
                *(uint32_t*)(Ol + (size_t)row * 512 + col) = bf2(v0 - h0, v1 - h1);
            }
        }
}

// ================= launcher =================
extern "C" void kernel_launch(void* const* d_in, const int* in_sizes, int n_in,
                              void* d_out, int out_size) {
    const float* x        = (const float*)d_in[0];
    const float* context  = (const float*)d_in[1];
    const float* context2 = (const float*)d_in[2];
    const float* context3 = (const float*)d_in[3];
    const void*  mask1 = d_in[4];
    const void*  mask2 = d_in[5];
    const void*  mask3 = d_in[6];
    const float* bq  = (const float*)d_in[8];
    const float* bk1 = (const float*)d_in[10];
    const float* bv1 = (const float*)d_in[12];
    const float* bk2 = (const float*)d_in[14];
    const float* bv2 = (const float*)d_in[16];
    const float* bk3 = (const float*)d_in[18];
    const float* bv3 = (const float*)d_in[20];
    const float* Wo  = (const float*)d_in[21];
    const float* bo  = (const float*)d_in[22];
    float* out = (float*)d_out;

    uint16_t *hp, *lp, *qbp, *kbp;
    float *vp;
    cudaGetSymbolAddress((void**)&hp,  g_h);
    cudaGetSymbolAddress((void**)&lp,  g_l);
    cudaGetSymbolAddress((void**)&qbp, g_qb);
    cudaGetSymbolAddress((void**)&kbp, g_kb);
    cudaGetSymbolAddress((void**)&vp,  g_v);

    const int smem_gemm = 2 * G_STW * 4;
    const int smem_attn = A_TOTW * 4;
    static bool once = false;
    static cudaStream_t s2;
    static cudaEvent_t ev1, ev2;
    if (!once) {
        cudaFuncSetAttribute(gemm_jobs, cudaFuncAttributeMaxDynamicSharedMemorySize, smem_gemm);
        cudaFuncSetAttribute(attn_mma, cudaFuncAttributeMaxDynamicSharedMemorySize, smem_attn);
        cudaStreamCreateWithFlags(&s2, cudaStreamNonBlocking);
        cudaEventCreateWithFlags(&ev1, cudaEventDisableTiming);
        cudaEventCreateWithFlags(&ev2, cudaEventDisableTiming);
        once = true;
    }

    cudaEventRecord(ev1, 0);
    cudaStreamWaitEvent(s2, ev1, 0);
    detect_mask_kernel<<<1, 256, 0, s2>>>((const unsigned char*)mask1);
    pack_mask_kernel<<<2048, 256, 0, s2>>>(mask1, mask2, mask3);
    cudaEventRecord(ev2, s2);

    {
        SplitJobs js;
        const float* srcs[12] = {x, context, context2, context3,
                                 (const float*)d_in[7], (const float*)d_in[9],
                                 (const float*)d_in[11], (const float*)d_in[13],
                                 (const float*)d_in[15], (const float*)d_in[17],
                                 (const float*)d_in[19], Wo};
        int offs[12] = {OFF_X, OFF_C1, OFF_C2, OFF_C3,
                        OFF_WQ, OFF_WK1, OFF_WV1, OFF_WK2, OFF_WV2,
                        OFF_WK3, OFF_WV3, OFF_WO};
        int cnts[12] = {512, 512, 768, 512, 64, 64, 64, 96, 96, 32, 32, 64};
        int cum = 0;
        for (int i = 0; i < 12; ++i) {
            js.src[i] = srcs[i]; js.off[i] = offs[i];
            js.nblk[i] = cum; cum += cnts[i];
        }
        js.nblk[12] = cum;
        split_kernel<<<cum, 256>>>(js, 12);
    }

    {
        GJobs J;
        int aoffs[7]  = {OFF_X, OFF_C1, OFF_C2, OFF_C3, OFF_C1, OFF_C2, OFF_C3};
        int woffs[7]  = {OFF_WQ, OFF_WK1, OFF_WK2, OFF_WK3, OFF_WV1, OFF_WV2, OFF_WV3};
        const float* biases[7] = {bq, bk1, bk2, bk3, bv1, bv2, bv3};
        void* Cs[7]   = {qbp, kbp, kbp, kbp, vp, vp, vp};
        int Ks[7]     = {512, 512, 768, 256, 512, 768, 256};
        int mbs[7]    = {10, 10, 10, 11, 10, 10, 11};   // log2(Mb)
        int ros[7]    = {0, 0, 1024, 2048, 0, 1024, 2048};
        int bss[7]    = {1024, 4096, 4096, 4096, 4096, 4096, 4096};
        int modes[7]  = {4, 2, 2, 2, 1, 1, 1};
        int blks[7]   = {256, 256, 256, 512, 256, 256, 512};
        int cum = 0;
        for (int i = 0; i < 7; ++i) {
            J.Ah[i] = hp + aoffs[i]; J.Al[i] = lp + aoffs[i];
            J.Wh[i] = hp + woffs[i]; J.Wl[i] = lp + woffs[i];
            J.bias[i] = biases[i]; J.C[i] = Cs[i];
            J.K[i] = Ks[i]; J.mbShift[i] = mbs[i]; J.rowOff[i] = ros[i];
            J.bStride[i] = bss[i]; J.mode[i] = modes[i];
            J.blk0[i] = cum; cum += blks[i];
        }
        J.blk0[7] = cum; J.njobs = 7;
        gemm_jobs<<<cum, 256, smem_gemm>>>(J);
    }

    cudaStreamWaitEvent(0, ev2, 0);

    attn_mma<<<dim3(8, 8, 4), 256, smem_attn>>>(qbp, kbp, vp, hp + OFF_AO, lp + OFF_AO);

    {
        GJobs J;
        J.Ah[0] = hp + OFF_AO; J.Al[0] = lp + OFF_AO;
        J.Wh[0] = hp + OFF_WO; J.Wl[0] = lp + OFF_WO;
        J.bias[0] = bo; J.C[0] = out;
        J.K[0] = 512; J.mbShift[0] = 10; J.rowOff[0] = 0;
        J.bStride[0] = 1024; J.mode[0] = 0;
        J.blk0[0] = 0; J.blk0[1] = 256; J.njobs = 1;
        gemm_jobs<<<256, 256, smem_gemm>>>(J);
    }
}